// round 1
// baseline (speedup 1.0000x reference)
#include <cuda_runtime.h>
#include <stdint.h>

#define N_NODES 50000
#define E_EDGES 500000
#define R_REL 8
#define HID 128
#define NRSEG (N_NODES * R_REL)      // 400000 segments
#define KA (R_REL * HID)             // 1024
#define NG 64
#define EPS_BN 1e-5f

typedef unsigned long long ull;

// ------------------------- device scratch (static, no allocs) ---------------
__device__ float g_agg[NRSEG * HID];          // 204.8 MB  mean-aggregated msgs
__device__ float g_h[N_NODES * HID];          // current hidden state
__device__ float g_raw[N_NODES * HID];        // pre-BN gemm output / t1
__device__ float g_emb[N_NODES * HID];        // node_emb (layer 3 out)
__device__ float g_gemb[NG * HID];            // pooled graph embeddings
__device__ int   g_src32[E_EDGES];
__device__ int   g_segid[E_EDGES];
__device__ int   g_srcsorted[E_EDGES];
__device__ int   g_hist[NRSEG];
__device__ int   g_segstart[NRSEG + 1];
__device__ int   g_cursor[NRSEG];
__device__ float g_inv[NRSEG];
__device__ int   g_batch32[N_NODES];
__device__ int   g_gstart[NG + 1];
__device__ float g_scores[N_NODES];
__device__ float g_attn[N_NODES];
__device__ float g_colstats[2 * HID];         // [0:128) colsum, [128:256) colsumsq
__device__ float g_bnscale[HID];
__device__ float g_bnshift[HID];
__device__ unsigned g_maxkey;
__device__ float g_sumexp;
__device__ int   g_is64;
__device__ int   g_bsums[512];

// ------------------------- helpers ------------------------------------------
__device__ __forceinline__ float lrelu(float x) { return x > 0.f ? x : 0.1f * x; }

__device__ __forceinline__ unsigned enc_f(float f) {
    unsigned b = __float_as_uint(f);
    return (b & 0x80000000u) ? ~b : (b | 0x80000000u);
}
__device__ __forceinline__ float dec_f(unsigned k) {
    unsigned b = (k & 0x80000000u) ? (k & 0x7FFFFFFFu) : ~k;
    return __uint_as_float(b);
}

#define USE_F32X2 1
__device__ __forceinline__ ull pk2(float x, float y) {
    ull r; asm("mov.b64 %0, {%1, %2};" : "=l"(r) : "f"(x), "f"(y)); return r;
}
__device__ __forceinline__ void upk2(ull v, float& x, float& y) {
    asm("mov.b64 {%0, %1}, %2;" : "=f"(x), "=f"(y) : "l"(v));
}
__device__ __forceinline__ ull ffma2(ull a, ull b, ull c) {
#if USE_F32X2
    ull d; asm("fma.rn.f32x2 %0, %1, %2, %3;" : "=l"(d) : "l"(a), "l"(b), "l"(c)); return d;
#else
    float ax, ay, bx, by, cx, cy;
    upk2(a, ax, ay); upk2(b, bx, by); upk2(c, cx, cy);
    return pk2(fmaf(ax, bx, cx), fmaf(ay, by, cy));
#endif
}

// ------------------------- dtype detection ----------------------------------
__global__ void k_detect(const ull* __restrict__ ei) {
    __shared__ unsigned s_is32;
    if (threadIdx.x == 0) s_is32 = 0;
    __syncthreads();
    ull m = 0;
    for (int i = threadIdx.x; i < 1024; i += 256) { ull v = ei[i]; m = v > m ? v : m; }
    if (m >= (1ull << 32)) atomicOr(&s_is32, 1u);
    __syncthreads();
    if (threadIdx.x == 0) g_is64 = s_is32 ? 0 : 1;
}

// ------------------------- edge preprocessing -------------------------------
__global__ void k_zero_hist() {
    int i = blockIdx.x * blockDim.x + threadIdx.x;
    if (i < NRSEG) g_hist[i] = 0;
}

__global__ void k_edge_prep(const void* __restrict__ ei, const void* __restrict__ et,
                            const void* __restrict__ bt) {
    int e = blockIdx.x * blockDim.x + threadIdx.x;
    int is64 = g_is64;
    if (e < E_EDGES) {
        int src, dst, ty;
        if (is64) {
            const long long* p = (const long long*)ei;
            src = (int)p[e]; dst = (int)p[E_EDGES + e];
            ty = (int)((const long long*)et)[e];
        } else {
            const int* p = (const int*)ei;
            src = p[e]; dst = p[E_EDGES + e];
            ty = ((const int*)et)[e];
        }
        g_src32[e] = src;
        int s = dst * R_REL + ty;
        g_segid[e] = s;
        atomicAdd(&g_hist[s], 1);
    }
    if (e < N_NODES) {
        g_batch32[e] = is64 ? (int)((const long long*)bt)[e] : ((const int*)bt)[e];
    }
}

__global__ void k_scan1() {
    __shared__ int sd[256];
    int t = threadIdx.x;
    int base = blockIdx.x * 1024 + t * 4;
    int v0 = 0, v1 = 0, v2 = 0, v3 = 0;
    if (base + 0 < NRSEG) v0 = g_hist[base + 0];
    if (base + 1 < NRSEG) v1 = g_hist[base + 1];
    if (base + 2 < NRSEG) v2 = g_hist[base + 2];
    if (base + 3 < NRSEG) v3 = g_hist[base + 3];
    int ts = v0 + v1 + v2 + v3;
    sd[t] = ts; __syncthreads();
    for (int off = 1; off < 256; off <<= 1) {
        int x = (t >= off) ? sd[t - off] : 0;
        __syncthreads();
        sd[t] += x;
        __syncthreads();
    }
    int ex = sd[t] - ts;
    if (base + 0 < NRSEG) g_segstart[base + 0] = ex;
    ex += v0; if (base + 1 < NRSEG) g_segstart[base + 1] = ex;
    ex += v1; if (base + 2 < NRSEG) g_segstart[base + 2] = ex;
    ex += v2; if (base + 3 < NRSEG) g_segstart[base + 3] = ex;
    if (t == 255) g_bsums[blockIdx.x] = sd[255];
}

__global__ void k_scan2(int nb) {
    __shared__ int sd[512];
    int t = threadIdx.x;
    int v = (t < nb) ? g_bsums[t] : 0;
    sd[t] = v; __syncthreads();
    for (int off = 1; off < 512; off <<= 1) {
        int x = (t >= off) ? sd[t - off] : 0;
        __syncthreads();
        sd[t] += x;
        __syncthreads();
    }
    if (t < nb) g_bsums[t] = sd[t] - v;
}

__global__ void k_scan3() {
    int i = blockIdx.x * blockDim.x + threadIdx.x;
    if (i < NRSEG) {
        int v = g_segstart[i] + g_bsums[i >> 10];
        g_segstart[i] = v;
        g_cursor[i] = v;
        int c = g_hist[i];
        g_inv[i] = 1.0f / (float)(c > 0 ? c : 1);
    }
    if (i == 0) g_segstart[NRSEG] = E_EDGES;
}

__global__ void k_permute() {
    int e = blockIdx.x * blockDim.x + threadIdx.x;
    if (e < E_EDGES) {
        int s = g_segid[e];
        int pos = atomicAdd(&g_cursor[s], 1);
        g_srcsorted[pos] = g_src32[e];
    }
}

// ------------------------- aggregation (mean per (dst,rel)) -----------------
__global__ void __launch_bounds__(256) k_aggregate(const float* __restrict__ h) {
    int warp = (blockIdx.x * blockDim.x + threadIdx.x) >> 5;
    int lane = threadIdx.x & 31;
    if (warp >= NRSEG) return;
    int beg = g_segstart[warp], end = g_segstart[warp + 1];
    float4 acc = make_float4(0.f, 0.f, 0.f, 0.f);
    const float4* h4 = (const float4*)h;
    for (int e = beg; e < end; e++) {
        int s = g_srcsorted[e];
        float4 v = h4[s * 32 + lane];
        acc.x += v.x; acc.y += v.y; acc.z += v.z; acc.w += v.w;
    }
    float inv = g_inv[warp];
    acc.x *= inv; acc.y *= inv; acc.z *= inv; acc.w *= inv;
    ((float4*)g_agg)[warp * 32 + lane] = acc;
}

// ------------------------- tiled GEMM ---------------------------------------
// MODE 0: layer w/ BN stats  A=[agg|h] K=1152  out=raw
// MODE 1: layer 3            A=[agg|h] K=1152  out=emb
// MODE 2: combiner 1         A=[emb|gemb[batch]] K=256, lrelu epilogue
// MODE 3: combiner 2         A=t1 K=128, row-normalize epilogue -> d_out
#define BM 64
#define BN 128
#define BK 16

template <int MODE>
__device__ __forceinline__ float fetchA(const float* __restrict__ Aa, const float* __restrict__ Ab,
                                        const int* __restrict__ batch, int n, int k) {
    if (MODE <= 1) return (k < KA) ? Aa[(size_t)n * KA + k] : Ab[(size_t)n * HID + (k - KA)];
    else if (MODE == 2) return (k < HID) ? Aa[(size_t)n * HID + k]
                                         : Ab[(size_t)batch[n] * HID + (k - HID)];
    else return Aa[(size_t)n * HID + k];
}

template <int MODE>
__device__ __forceinline__ float fetchB(const float* __restrict__ B1, const float* __restrict__ B2,
                                        int k, int c) {
    if (MODE <= 1) return (k < KA) ? B1[k * HID + c] : B2[(k - KA) * HID + c];
    else return B1[k * HID + c];
}

template <int MODE, int KT>
__global__ void __launch_bounds__(256) k_gemm(const float* __restrict__ Aa,
                                              const float* __restrict__ Ab,
                                              const int* __restrict__ batch,
                                              const float* __restrict__ B1,
                                              const float* __restrict__ B2,
                                              const float* __restrict__ bias,
                                              float* __restrict__ out) {
    __shared__ __align__(16) float As[BK][BM + 4];
    __shared__ __align__(16) float Bs[BK][BN];
    __shared__ float s_sum[BN];
    __shared__ float s_ssq[BN];
    __shared__ float s_rs[BM][33];
    __shared__ float s_scale[BM];

    int tid = threadIdx.x;
    int bm = blockIdx.x * BM;
    int tr = tid >> 5;       // 0..7 row group
    int tc = tid & 31;       // 0..31 col group
    int lr = tid >> 4;       // 0..15
    int lk = tid & 15;

    ull acc[4][4];
#pragma unroll
    for (int p = 0; p < 4; p++)
#pragma unroll
        for (int j = 0; j < 4; j++) acc[p][j] = 0ull;

    for (int k0 = 0; k0 < KT; k0 += BK) {
#pragma unroll
        for (int p = 0; p < 4; p++) {
            int row = p * 16 + lr;
            int n = bm + row;
            float v = 0.f;
            if (n < N_NODES) v = fetchA<MODE>(Aa, Ab, batch, n, k0 + lk);
            As[lk][row] = v;
        }
#pragma unroll
        for (int p = 0; p < 8; p++) {
            int kk = p * 2 + (tid >> 7);
            int c = tid & 127;
            Bs[kk][c] = fetchB<MODE>(B1, B2, k0 + kk, c);
        }
        __syncthreads();
#pragma unroll
        for (int kk = 0; kk < BK; kk++) {
            const float* ap = &As[kk][tr * 8];
            ull a0 = *(const ull*)(ap + 0);
            ull a1 = *(const ull*)(ap + 2);
            ull a2 = *(const ull*)(ap + 4);
            ull a3 = *(const ull*)(ap + 6);
            float4 b4 = *(const float4*)&Bs[kk][tc * 4];
            ull b0 = pk2(b4.x, b4.x), b1 = pk2(b4.y, b4.y);
            ull b2 = pk2(b4.z, b4.z), b3 = pk2(b4.w, b4.w);
            acc[0][0] = ffma2(a0, b0, acc[0][0]); acc[0][1] = ffma2(a0, b1, acc[0][1]);
            acc[0][2] = ffma2(a0, b2, acc[0][2]); acc[0][3] = ffma2(a0, b3, acc[0][3]);
            acc[1][0] = ffma2(a1, b0, acc[1][0]); acc[1][1] = ffma2(a1, b1, acc[1][1]);
            acc[1][2] = ffma2(a1, b2, acc[1][2]); acc[1][3] = ffma2(a1, b3, acc[1][3]);
            acc[2][0] = ffma2(a2, b0, acc[2][0]); acc[2][1] = ffma2(a2, b1, acc[2][1]);
            acc[2][2] = ffma2(a2, b2, acc[2][2]); acc[2][3] = ffma2(a2, b3, acc[2][3]);
            acc[3][0] = ffma2(a3, b0, acc[3][0]); acc[3][1] = ffma2(a3, b1, acc[3][1]);
            acc[3][2] = ffma2(a3, b2, acc[3][2]); acc[3][3] = ffma2(a3, b3, acc[3][3]);
        }
        __syncthreads();
    }

    // unpack + bias
    float fv[8][4];
#pragma unroll
    for (int p = 0; p < 4; p++)
#pragma unroll
        for (int j = 0; j < 4; j++) {
            float x, y;
            upk2(acc[p][j], x, y);
            fv[2 * p + 0][j] = x;
            fv[2 * p + 1][j] = y;
        }
    float4 bb4 = *(const float4*)&bias[tc * 4];
    float bb[4] = {bb4.x, bb4.y, bb4.z, bb4.w};
#pragma unroll
    for (int r = 0; r < 8; r++)
#pragma unroll
        for (int j = 0; j < 4; j++) {
            fv[r][j] += bb[j];
            if (MODE == 2) fv[r][j] = lrelu(fv[r][j]);
        }

    if (MODE == 0) {
        // BN column stats over valid rows
        if (tid < BN) { s_sum[tid] = 0.f; s_ssq[tid] = 0.f; }
        __syncthreads();
        float ps[4] = {0, 0, 0, 0}, pq[4] = {0, 0, 0, 0};
#pragma unroll
        for (int r = 0; r < 8; r++) {
            int n = bm + tr * 8 + r;
            if (n < N_NODES) {
#pragma unroll
                for (int j = 0; j < 4; j++) { float v = fv[r][j]; ps[j] += v; pq[j] += v * v; }
            }
        }
#pragma unroll
        for (int j = 0; j < 4; j++) {
            atomicAdd(&s_sum[tc * 4 + j], ps[j]);
            atomicAdd(&s_ssq[tc * 4 + j], pq[j]);
        }
        __syncthreads();
        if (tid < BN) {
            atomicAdd(&g_colstats[tid], s_sum[tid]);
            atomicAdd(&g_colstats[HID + tid], s_ssq[tid]);
        }
    }

    if (MODE == 3) {
        // row normalization
#pragma unroll
        for (int r = 0; r < 8; r++) {
            float q = 0.f;
#pragma unroll
            for (int j = 0; j < 4; j++) q += fv[r][j] * fv[r][j];
            s_rs[tr * 8 + r][tc] = q;
        }
        __syncthreads();
        if (tid < BM) {
            float s = 0.f;
            for (int t2 = 0; t2 < 32; t2++) s += s_rs[tid][t2];
            float nrm = sqrtf(s);
            s_scale[tid] = 1.f / fmaxf(nrm, 1e-12f);
        }
        __syncthreads();
#pragma unroll
        for (int r = 0; r < 8; r++) {
            float sc = s_scale[tr * 8 + r];
#pragma unroll
            for (int j = 0; j < 4; j++) fv[r][j] *= sc;
        }
    }

#pragma unroll
    for (int r = 0; r < 8; r++) {
        int n = bm + tr * 8 + r;
        if (n < N_NODES) {
            float4 o = make_float4(fv[r][0], fv[r][1], fv[r][2], fv[r][3]);
            *(float4*)&out[(size_t)n * HID + tc * 4] = o;
        }
    }
}

// ------------------------- BN -----------------------------------------------
__global__ void k_zero_small() {
    int t = threadIdx.x;
    if (t < 256) g_colstats[t] = 0.f;
    if (t == 0) { g_maxkey = 0u; g_sumexp = 0.f; }
}

__global__ void k_bnfin(const float* __restrict__ gamma, const float* __restrict__ beta) {
    int c = threadIdx.x;
    if (c < HID) {
        float inv_n = 1.f / (float)N_NODES;
        float mu = g_colstats[c] * inv_n;
        float var = fmaxf(g_colstats[HID + c] * inv_n - mu * mu, 0.f);
        float sc = gamma[c] * rsqrtf(var + EPS_BN);
        g_bnscale[c] = sc;
        g_bnshift[c] = beta[c] - mu * sc;
    }
}

__global__ void k_bnapply() {
    int i = blockIdx.x * blockDim.x + threadIdx.x;   // float4 index
    if (i < N_NODES * 32) {
        float4 v = ((const float4*)g_raw)[i];
        int c4 = i & 31;
        float4 sc = ((const float4*)g_bnscale)[c4];
        float4 sh = ((const float4*)g_bnshift)[c4];
        float4 o;
        o.x = lrelu(v.x * sc.x + sh.x);
        o.y = lrelu(v.y * sc.y + sh.y);
        o.z = lrelu(v.z * sc.z + sh.z);
        o.w = lrelu(v.w * sc.w + sh.w);
        ((float4*)g_h)[i] = o;
    }
}

// ------------------------- attention ----------------------------------------
__global__ void __launch_bounds__(256) k_scores(const float* __restrict__ A1,
                                                const float* __restrict__ a1,
                                                const float* __restrict__ A2,
                                                const float* __restrict__ a2v) {
    __shared__ float sA1[HID * 64];
    __shared__ float sA2[64];
    __shared__ float sa1[64];
    __shared__ float se[8][HID];
    __shared__ unsigned s_bmax;
    int tid = threadIdx.x;
    for (int i = tid; i < HID * 64; i += 256) sA1[i] = A1[i];
    if (tid < 64) { sA2[tid] = A2[tid]; sa1[tid] = a1[tid]; }
    if (tid == 0) s_bmax = 0u;
    __syncthreads();
    int w = tid >> 5, lane = tid & 31;
    unsigned localmax = 0u;
    float a2s = a2v[0];
    for (int n = blockIdx.x * 8 + w; n < N_NODES; n += gridDim.x * 8) {
        for (int i = lane; i < HID; i += 32) se[w][i] = g_emb[(size_t)n * HID + i];
        __syncwarp();
        float acc0 = 0.f, acc1 = 0.f;
#pragma unroll 8
        for (int k = 0; k < HID; k++) {
            float e = se[w][k];
            acc0 = fmaf(e, sA1[k * 64 + lane], acc0);
            acc1 = fmaf(e, sA1[k * 64 + lane + 32], acc1);
        }
        acc0 = lrelu(acc0 + sa1[lane]);
        acc1 = lrelu(acc1 + sa1[lane + 32]);
        float part = acc0 * sA2[lane] + acc1 * sA2[lane + 32];
#pragma unroll
        for (int off = 16; off > 0; off >>= 1) part += __shfl_down_sync(0xFFFFFFFFu, part, off);
        if (lane == 0) {
            float s = part + a2s;
            g_scores[n] = s;
            unsigned k = enc_f(s);
            localmax = k > localmax ? k : localmax;
        }
        __syncwarp();
    }
    if (lane == 0 && localmax) atomicMax(&s_bmax, localmax);
    __syncthreads();
    if (tid == 0) atomicMax(&g_maxkey, s_bmax);
}

__global__ void k_sumexp() {
    __shared__ float sred[256];
    int n = blockIdx.x * blockDim.x + threadIdx.x;
    float gmax = dec_f(g_maxkey);
    float v = (n < N_NODES) ? expf(g_scores[n] - gmax) : 0.f;
    sred[threadIdx.x] = v;
    __syncthreads();
    for (int off = 128; off > 0; off >>= 1) {
        if (threadIdx.x < off) sred[threadIdx.x] += sred[threadIdx.x + off];
        __syncthreads();
    }
    if (threadIdx.x == 0) atomicAdd(&g_sumexp, sred[0]);
}

__global__ void k_attn() {
    int n = blockIdx.x * blockDim.x + threadIdx.x;
    if (n < N_NODES) {
        float gmax = dec_f(g_maxkey);
        g_attn[n] = expf(g_scores[n] - gmax) / g_sumexp;
    }
}

__global__ void k_gbounds() {
    int i = blockIdx.x * blockDim.x + threadIdx.x;
    if (i <= N_NODES) {
        int cur = (i < N_NODES) ? g_batch32[i] : NG;
        int prev = (i == 0) ? -1 : g_batch32[i - 1];
        for (int g = prev + 1; g <= cur && g <= NG; g++) g_gstart[g] = i;
    }
}

__global__ void k_pool() {
    int g = blockIdx.x, c = threadIdx.x;
    float acc = 0.f;
    int b = g_gstart[g], e = g_gstart[g + 1];
    for (int n = b; n < e; n++) acc += g_emb[(size_t)n * HID + c] * g_attn[n];
    g_gemb[g * HID + c] = acc;
}

// ------------------------- host launcher ------------------------------------
extern "C" void kernel_launch(void* const* d_in, const int* in_sizes, int n_in,
                              void* d_out, int out_size) {
    const float* x     = (const float*)d_in[0];
    const void*  ei    = d_in[1];
    const void*  et    = d_in[2];
    const void*  bt    = d_in[3];
    const float* W1    = (const float*)d_in[4];
    const float* root1 = (const float*)d_in[5];
    const float* b1    = (const float*)d_in[6];
    const float* W2    = (const float*)d_in[7];
    const float* root2 = (const float*)d_in[8];
    const float* b2    = (const float*)d_in[9];
    const float* W3    = (const float*)d_in[10];
    const float* root3 = (const float*)d_in[11];
    const float* b3    = (const float*)d_in[12];
    const float* g1    = (const float*)d_in[13];
    const float* beta1 = (const float*)d_in[14];
    const float* g2    = (const float*)d_in[15];
    const float* beta2 = (const float*)d_in[16];
    const float* A1    = (const float*)d_in[17];
    const float* a1    = (const float*)d_in[18];
    const float* A2    = (const float*)d_in[19];
    const float* a2    = (const float*)d_in[20];
    const float* C1    = (const float*)d_in[21];
    const float* c1    = (const float*)d_in[22];
    const float* C2    = (const float*)d_in[23];
    const float* c2    = (const float*)d_in[24];
    float* out = (float*)d_out;

    void *p_agg, *p_h, *p_raw, *p_emb, *p_gemb, *p_batch;
    cudaGetSymbolAddress(&p_agg, g_agg);
    cudaGetSymbolAddress(&p_h, g_h);
    cudaGetSymbolAddress(&p_raw, g_raw);
    cudaGetSymbolAddress(&p_emb, g_emb);
    cudaGetSymbolAddress(&p_gemb, g_gemb);
    cudaGetSymbolAddress(&p_batch, g_batch32);
    float* agg  = (float*)p_agg;
    float* h    = (float*)p_h;
    float* raw  = (float*)p_raw;
    float* emb  = (float*)p_emb;
    float* gemb = (float*)p_gemb;
    int* batch32 = (int*)p_batch;

    const int NB1 = (NRSEG + 1023) / 1024;   // 391

    // --- edge preprocessing (counting sort by segment) ---
    k_detect<<<1, 256>>>((const ull*)ei);
    k_zero_hist<<<(NRSEG + 255) / 256, 256>>>();
    k_edge_prep<<<(E_EDGES + 255) / 256, 256>>>(ei, et, bt);
    k_scan1<<<NB1, 256>>>();
    k_scan2<<<1, 512>>>(NB1);
    k_scan3<<<(NRSEG + 255) / 256, 256>>>();
    k_permute<<<(E_EDGES + 255) / 256, 256>>>();

    const int GEMM_BLOCKS = (N_NODES + BM - 1) / BM;   // 782
    const int AGG_BLOCKS = NRSEG / 8;                  // 50000

    // --- layer 1 ---
    k_aggregate<<<AGG_BLOCKS, 256>>>(x);
    k_zero_small<<<1, 256>>>();
    k_gemm<0, 1152><<<GEMM_BLOCKS, 256>>>(agg, x, nullptr, W1, root1, b1, raw);
    k_bnfin<<<1, 128>>>(g1, beta1);
    k_bnapply<<<(N_NODES * 32 + 255) / 256, 256>>>();

    // --- layer 2 ---
    k_aggregate<<<AGG_BLOCKS, 256>>>(h);
    k_zero_small<<<1, 256>>>();
    k_gemm<0, 1152><<<GEMM_BLOCKS, 256>>>(agg, h, nullptr, W2, root2, b2, raw);
    k_bnfin<<<1, 128>>>(g2, beta2);
    k_bnapply<<<(N_NODES * 32 + 255) / 256, 256>>>();

    // --- layer 3 (no BN) ---
    k_aggregate<<<AGG_BLOCKS, 256>>>(h);
    k_gemm<1, 1152><<<GEMM_BLOCKS, 256>>>(agg, h, nullptr, W3, root3, b3, emb);

    // --- attention pooling ---
    k_zero_small<<<1, 256>>>();
    k_scores<<<512, 256>>>(A1, a1, A2, a2);
    k_sumexp<<<(N_NODES + 255) / 256, 256>>>();
    k_attn<<<(N_NODES + 255) / 256, 256>>>();
    k_gbounds<<<(N_NODES + 256) / 256, 256>>>();
    k_pool<<<NG, 128>>>();

    // --- combiner MLP + row normalize ---
    k_gemm<2, 256><<<GEMM_BLOCKS, 256>>>(emb, gemb, batch32, C1, nullptr, c1, raw);
    k_gemm<3, 128><<<GEMM_BLOCKS, 256>>>(raw, nullptr, nullptr, C2, nullptr, c2, out);

    (void)in_sizes; (void)n_in; (void)out_size;
}

// round 2
// speedup vs baseline: 1.0002x; 1.0002x over previous
#include <cuda_runtime.h>
#include <stdint.h>

#define N_NODES 50000
#define E_EDGES 500000
#define R_REL 8
#define HID 128
#define NRSEG (N_NODES * R_REL)      // 400000 segments
#define KA (R_REL * HID)             // 1024
#define NG 64
#define EPS_BN 1e-5f

typedef unsigned long long ull;

// ------------------------- device scratch (static, no allocs) ---------------
__device__ float g_agg[NRSEG * HID];          // 204.8 MB  mean-aggregated msgs
__device__ float g_h[N_NODES * HID];          // current hidden state
__device__ float g_raw[N_NODES * HID];        // pre-BN gemm output / t1
__device__ float g_emb[N_NODES * HID];        // node_emb (layer 3 out)
__device__ float g_gemb[NG * HID];            // pooled graph embeddings
__device__ int   g_src32[E_EDGES];
__device__ int   g_segid[E_EDGES];
__device__ int   g_srcsorted[E_EDGES];
__device__ int   g_hist[NRSEG];
__device__ int   g_segstart[NRSEG + 1];
__device__ int   g_cursor[NRSEG];
__device__ float g_inv[NRSEG];
__device__ int   g_batch32[N_NODES];
__device__ int   g_gstart[NG + 1];
__device__ float g_scores[N_NODES];
__device__ float g_attn[N_NODES];
__device__ float g_colstats[2 * HID];         // [0:128) colsum, [128:256) colsumsq
__device__ float g_bnscale[HID];
__device__ float g_bnshift[HID];
__device__ unsigned g_maxkey;
__device__ float g_sumexp;
__device__ int   g_is64;
__device__ int   g_bsums[512];

// ------------------------- helpers ------------------------------------------
__device__ __forceinline__ float lrelu(float x) { return x > 0.f ? x : 0.1f * x; }

__device__ __forceinline__ unsigned enc_f(float f) {
    unsigned b = __float_as_uint(f);
    return (b & 0x80000000u) ? ~b : (b | 0x80000000u);
}
__device__ __forceinline__ float dec_f(unsigned k) {
    unsigned b = (k & 0x80000000u) ? (k & 0x7FFFFFFFu) : ~k;
    return __uint_as_float(b);
}

#define USE_F32X2 1
__device__ __forceinline__ ull pk2(float x, float y) {
    ull r; asm("mov.b64 %0, {%1, %2};" : "=l"(r) : "f"(x), "f"(y)); return r;
}
__device__ __forceinline__ void upk2(ull v, float& x, float& y) {
    asm("mov.b64 {%0, %1}, %2;" : "=f"(x), "=f"(y) : "l"(v));
}
__device__ __forceinline__ ull ffma2(ull a, ull b, ull c) {
#if USE_F32X2
    ull d; asm("fma.rn.f32x2 %0, %1, %2, %3;" : "=l"(d) : "l"(a), "l"(b), "l"(c)); return d;
#else
    float ax, ay, bx, by, cx, cy;
    upk2(a, ax, ay); upk2(b, bx, by); upk2(c, cx, cy);
    return pk2(fmaf(ax, bx, cx), fmaf(ay, by, cy));
#endif
}

// ------------------------- dtype detection ----------------------------------
__global__ void k_detect(const ull* __restrict__ ei) {
    __shared__ unsigned s_is32;
    if (threadIdx.x == 0) s_is32 = 0;
    __syncthreads();
    ull m = 0;
    for (int i = threadIdx.x; i < 1024; i += 256) { ull v = ei[i]; m = v > m ? v : m; }
    if (m >= (1ull << 32)) atomicOr(&s_is32, 1u);
    __syncthreads();
    if (threadIdx.x == 0) g_is64 = s_is32 ? 0 : 1;
}

// ------------------------- edge preprocessing -------------------------------
__global__ void k_zero_hist() {
    int i = blockIdx.x * blockDim.x + threadIdx.x;
    if (i < NRSEG) g_hist[i] = 0;
}

__global__ void k_edge_prep(const void* __restrict__ ei, const void* __restrict__ et,
                            const void* __restrict__ bt) {
    int e = blockIdx.x * blockDim.x + threadIdx.x;
    int is64 = g_is64;
    if (e < E_EDGES) {
        int src, dst, ty;
        if (is64) {
            const long long* p = (const long long*)ei;
            src = (int)p[e]; dst = (int)p[E_EDGES + e];
            ty = (int)((const long long*)et)[e];
        } else {
            const int* p = (const int*)ei;
            src = p[e]; dst = p[E_EDGES + e];
            ty = ((const int*)et)[e];
        }
        g_src32[e] = src;
        int s = dst * R_REL + ty;
        g_segid[e] = s;
        atomicAdd(&g_hist[s], 1);
    }
    if (e < N_NODES) {
        g_batch32[e] = is64 ? (int)((const long long*)bt)[e] : ((const int*)bt)[e];
    }
}

__global__ void k_scan1() {
    __shared__ int sd[256];
    int t = threadIdx.x;
    int base = blockIdx.x * 1024 + t * 4;
    int v0 = 0, v1 = 0, v2 = 0, v3 = 0;
    if (base + 0 < NRSEG) v0 = g_hist[base + 0];
    if (base + 1 < NRSEG) v1 = g_hist[base + 1];
    if (base + 2 < NRSEG) v2 = g_hist[base + 2];
    if (base + 3 < NRSEG) v3 = g_hist[base + 3];
    int ts = v0 + v1 + v2 + v3;
    sd[t] = ts; __syncthreads();
    for (int off = 1; off < 256; off <<= 1) {
        int x = (t >= off) ? sd[t - off] : 0;
        __syncthreads();
        sd[t] += x;
        __syncthreads();
    }
    int ex = sd[t] - ts;
    if (base + 0 < NRSEG) g_segstart[base + 0] = ex;
    ex += v0; if (base + 1 < NRSEG) g_segstart[base + 1] = ex;
    ex += v1; if (base + 2 < NRSEG) g_segstart[base + 2] = ex;
    ex += v2; if (base + 3 < NRSEG) g_segstart[base + 3] = ex;
    if (t == 255) g_bsums[blockIdx.x] = sd[255];
}

__global__ void k_scan2(int nb) {
    __shared__ int sd[512];
    int t = threadIdx.x;
    int v = (t < nb) ? g_bsums[t] : 0;
    sd[t] = v; __syncthreads();
    for (int off = 1; off < 512; off <<= 1) {
        int x = (t >= off) ? sd[t - off] : 0;
        __syncthreads();
        sd[t] += x;
        __syncthreads();
    }
    if (t < nb) g_bsums[t] = sd[t] - v;
}

__global__ void k_scan3() {
    int i = blockIdx.x * blockDim.x + threadIdx.x;
    if (i < NRSEG) {
        int v = g_segstart[i] + g_bsums[i >> 10];
        g_segstart[i] = v;
        g_cursor[i] = v;
        int c = g_hist[i];
        g_inv[i] = 1.0f / (float)(c > 0 ? c : 1);
    }
    if (i == 0) g_segstart[NRSEG] = E_EDGES;
}

__global__ void k_permute() {
    int e = blockIdx.x * blockDim.x + threadIdx.x;
    if (e < E_EDGES) {
        int s = g_segid[e];
        int pos = atomicAdd(&g_cursor[s], 1);
        g_srcsorted[pos] = g_src32[e];
    }
}

// ------------------------- aggregation (mean per (dst,rel)) -----------------
__global__ void __launch_bounds__(256) k_aggregate(const float* __restrict__ h) {
    int warp = (blockIdx.x * blockDim.x + threadIdx.x) >> 5;
    int lane = threadIdx.x & 31;
    if (warp >= NRSEG) return;
    int beg = g_segstart[warp], end = g_segstart[warp + 1];
    float4 acc = make_float4(0.f, 0.f, 0.f, 0.f);
    const float4* h4 = (const float4*)h;
    for (int e = beg; e < end; e++) {
        int s = g_srcsorted[e];
        float4 v = h4[s * 32 + lane];
        acc.x += v.x; acc.y += v.y; acc.z += v.z; acc.w += v.w;
    }
    float inv = g_inv[warp];
    acc.x *= inv; acc.y *= inv; acc.z *= inv; acc.w *= inv;
    ((float4*)g_agg)[warp * 32 + lane] = acc;
}

// ------------------------- tiled GEMM ---------------------------------------
// MODE 0: layer w/ BN stats  A=[agg|h] K=1152  out=raw
// MODE 1: layer 3            A=[agg|h] K=1152  out=emb
// MODE 2: combiner 1         A=[emb|gemb[batch]] K=256, lrelu epilogue
// MODE 3: combiner 2         A=t1 K=128, row-normalize epilogue -> d_out
#define BM 64
#define BN 128
#define BK 16

template <int MODE>
__device__ __forceinline__ float fetchA(const float* __restrict__ Aa, const float* __restrict__ Ab,
                                        const int* __restrict__ batch, int n, int k) {
    if (MODE <= 1) return (k < KA) ? Aa[(size_t)n * KA + k] : Ab[(size_t)n * HID + (k - KA)];
    else if (MODE == 2) return (k < HID) ? Aa[(size_t)n * HID + k]
                                         : Ab[(size_t)batch[n] * HID + (k - HID)];
    else return Aa[(size_t)n * HID + k];
}

template <int MODE>
__device__ __forceinline__ float fetchB(const float* __restrict__ B1, const float* __restrict__ B2,
                                        int k, int c) {
    if (MODE <= 1) return (k < KA) ? B1[k * HID + c] : B2[(k - KA) * HID + c];
    else return B1[k * HID + c];
}

template <int MODE, int KT>
__global__ void __launch_bounds__(256) k_gemm(const float* __restrict__ Aa,
                                              const float* __restrict__ Ab,
                                              const int* __restrict__ batch,
                                              const float* __restrict__ B1,
                                              const float* __restrict__ B2,
                                              const float* __restrict__ bias,
                                              float* __restrict__ out) {
    __shared__ __align__(16) float As[BK][BM + 4];
    __shared__ __align__(16) float Bs[BK][BN];
    __shared__ float s_sum[BN];
    __shared__ float s_ssq[BN];
    __shared__ float s_rs[BM][33];
    __shared__ float s_scale[BM];

    int tid = threadIdx.x;
    int bm = blockIdx.x * BM;
    int tr = tid >> 5;       // 0..7 row group
    int tc = tid & 31;       // 0..31 col group
    int lr = tid >> 4;       // 0..15
    int lk = tid & 15;

    ull acc[4][4];
#pragma unroll
    for (int p = 0; p < 4; p++)
#pragma unroll
        for (int j = 0; j < 4; j++) acc[p][j] = 0ull;

    for (int k0 = 0; k0 < KT; k0 += BK) {
#pragma unroll
        for (int p = 0; p < 4; p++) {
            int row = p * 16 + lr;
            int n = bm + row;
            float v = 0.f;
            if (n < N_NODES) v = fetchA<MODE>(Aa, Ab, batch, n, k0 + lk);
            As[lk][row] = v;
        }
#pragma unroll
        for (int p = 0; p < 8; p++) {
            int kk = p * 2 + (tid >> 7);
            int c = tid & 127;
            Bs[kk][c] = fetchB<MODE>(B1, B2, k0 + kk, c);
        }
        __syncthreads();
#pragma unroll
        for (int kk = 0; kk < BK; kk++) {
            const float* ap = &As[kk][tr * 8];
            ull a0 = *(const ull*)(ap + 0);
            ull a1 = *(const ull*)(ap + 2);
            ull a2 = *(const ull*)(ap + 4);
            ull a3 = *(const ull*)(ap + 6);
            float4 b4 = *(const float4*)&Bs[kk][tc * 4];
            ull b0 = pk2(b4.x, b4.x), b1 = pk2(b4.y, b4.y);
            ull b2 = pk2(b4.z, b4.z), b3 = pk2(b4.w, b4.w);
            acc[0][0] = ffma2(a0, b0, acc[0][0]); acc[0][1] = ffma2(a0, b1, acc[0][1]);
            acc[0][2] = ffma2(a0, b2, acc[0][2]); acc[0][3] = ffma2(a0, b3, acc[0][3]);
            acc[1][0] = ffma2(a1, b0, acc[1][0]); acc[1][1] = ffma2(a1, b1, acc[1][1]);
            acc[1][2] = ffma2(a1, b2, acc[1][2]); acc[1][3] = ffma2(a1, b3, acc[1][3]);
            acc[2][0] = ffma2(a2, b0, acc[2][0]); acc[2][1] = ffma2(a2, b1, acc[2][1]);
            acc[2][2] = ffma2(a2, b2, acc[2][2]); acc[2][3] = ffma2(a2, b3, acc[2][3]);
            acc[3][0] = ffma2(a3, b0, acc[3][0]); acc[3][1] = ffma2(a3, b1, acc[3][1]);
            acc[3][2] = ffma2(a3, b2, acc[3][2]); acc[3][3] = ffma2(a3, b3, acc[3][3]);
        }
        __syncthreads();
    }

    // unpack + bias
    float fv[8][4];
#pragma unroll
    for (int p = 0; p < 4; p++)
#pragma unroll
        for (int j = 0; j < 4; j++) {
            float x, y;
            upk2(acc[p][j], x, y);
            fv[2 * p + 0][j] = x;
            fv[2 * p + 1][j] = y;
        }
    float4 bb4 = *(const float4*)&bias[tc * 4];
    float bb[4] = {bb4.x, bb4.y, bb4.z, bb4.w};
#pragma unroll
    for (int r = 0; r < 8; r++)
#pragma unroll
        for (int j = 0; j < 4; j++) {
            fv[r][j] += bb[j];
            if (MODE == 2) fv[r][j] = lrelu(fv[r][j]);
        }

    if (MODE == 0) {
        // BN column stats over valid rows
        if (tid < BN) { s_sum[tid] = 0.f; s_ssq[tid] = 0.f; }
        __syncthreads();
        float ps[4] = {0, 0, 0, 0}, pq[4] = {0, 0, 0, 0};
#pragma unroll
        for (int r = 0; r < 8; r++) {
            int n = bm + tr * 8 + r;
            if (n < N_NODES) {
#pragma unroll
                for (int j = 0; j < 4; j++) { float v = fv[r][j]; ps[j] += v; pq[j] += v * v; }
            }
        }
#pragma unroll
        for (int j = 0; j < 4; j++) {
            atomicAdd(&s_sum[tc * 4 + j], ps[j]);
            atomicAdd(&s_ssq[tc * 4 + j], pq[j]);
        }
        __syncthreads();
        if (tid < BN) {
            atomicAdd(&g_colstats[tid], s_sum[tid]);
            atomicAdd(&g_colstats[HID + tid], s_ssq[tid]);
        }
    }

    if (MODE == 3) {
        // row normalization
#pragma unroll
        for (int r = 0; r < 8; r++) {
            float q = 0.f;
#pragma unroll
            for (int j = 0; j < 4; j++) q += fv[r][j] * fv[r][j];
            s_rs[tr * 8 + r][tc] = q;
        }
        __syncthreads();
        if (tid < BM) {
            float s = 0.f;
            for (int t2 = 0; t2 < 32; t2++) s += s_rs[tid][t2];
            float nrm = sqrtf(s);
            s_scale[tid] = 1.f / fmaxf(nrm, 1e-12f);
        }
        __syncthreads();
#pragma unroll
        for (int r = 0; r < 8; r++) {
            float sc = s_scale[tr * 8 + r];
#pragma unroll
            for (int j = 0; j < 4; j++) fv[r][j] *= sc;
        }
    }

#pragma unroll
    for (int r = 0; r < 8; r++) {
        int n = bm + tr * 8 + r;
        if (n < N_NODES) {
            float4 o = make_float4(fv[r][0], fv[r][1], fv[r][2], fv[r][3]);
            *(float4*)&out[(size_t)n * HID + tc * 4] = o;
        }
    }
}

// ------------------------- BN -----------------------------------------------
__global__ void k_zero_small() {
    int t = threadIdx.x;
    if (t < 256) g_colstats[t] = 0.f;
    if (t == 0) { g_maxkey = 0u; g_sumexp = 0.f; }
}

__global__ void k_bnfin(const float* __restrict__ gamma, const float* __restrict__ beta) {
    int c = threadIdx.x;
    if (c < HID) {
        float inv_n = 1.f / (float)N_NODES;
        float mu = g_colstats[c] * inv_n;
        float var = fmaxf(g_colstats[HID + c] * inv_n - mu * mu, 0.f);
        float sc = gamma[c] * rsqrtf(var + EPS_BN);
        g_bnscale[c] = sc;
        g_bnshift[c] = beta[c] - mu * sc;
    }
}

__global__ void k_bnapply() {
    int i = blockIdx.x * blockDim.x + threadIdx.x;   // float4 index
    if (i < N_NODES * 32) {
        float4 v = ((const float4*)g_raw)[i];
        int c4 = i & 31;
        float4 sc = ((const float4*)g_bnscale)[c4];
        float4 sh = ((const float4*)g_bnshift)[c4];
        float4 o;
        o.x = lrelu(v.x * sc.x + sh.x);
        o.y = lrelu(v.y * sc.y + sh.y);
        o.z = lrelu(v.z * sc.z + sh.z);
        o.w = lrelu(v.w * sc.w + sh.w);
        ((float4*)g_h)[i] = o;
    }
}

// ------------------------- attention ----------------------------------------
__global__ void __launch_bounds__(256) k_scores(const float* __restrict__ A1,
                                                const float* __restrict__ a1,
                                                const float* __restrict__ A2,
                                                const float* __restrict__ a2v) {
    __shared__ float sA1[HID * 64];
    __shared__ float sA2[64];
    __shared__ float sa1[64];
    __shared__ float se[8][HID];
    __shared__ unsigned s_bmax;
    int tid = threadIdx.x;
    for (int i = tid; i < HID * 64; i += 256) sA1[i] = A1[i];
    if (tid < 64) { sA2[tid] = A2[tid]; sa1[tid] = a1[tid]; }
    if (tid == 0) s_bmax = 0u;
    __syncthreads();
    int w = tid >> 5, lane = tid & 31;
    unsigned localmax = 0u;
    float a2s = a2v[0];
    for (int n = blockIdx.x * 8 + w; n < N_NODES; n += gridDim.x * 8) {
        for (int i = lane; i < HID; i += 32) se[w][i] = g_emb[(size_t)n * HID + i];
        __syncwarp();
        float acc0 = 0.f, acc1 = 0.f;
#pragma unroll 8
        for (int k = 0; k < HID; k++) {
            float e = se[w][k];
            acc0 = fmaf(e, sA1[k * 64 + lane], acc0);
            acc1 = fmaf(e, sA1[k * 64 + lane + 32], acc1);
        }
        acc0 = lrelu(acc0 + sa1[lane]);
        acc1 = lrelu(acc1 + sa1[lane + 32]);
        float part = acc0 * sA2[lane] + acc1 * sA2[lane + 32];
#pragma unroll
        for (int off = 16; off > 0; off >>= 1) part += __shfl_down_sync(0xFFFFFFFFu, part, off);
        if (lane == 0) {
            float s = part + a2s;
            g_scores[n] = s;
            unsigned k = enc_f(s);
            localmax = k > localmax ? k : localmax;
        }
        __syncwarp();
    }
    if (lane == 0 && localmax) atomicMax(&s_bmax, localmax);
    __syncthreads();
    if (tid == 0) atomicMax(&g_maxkey, s_bmax);
}

__global__ void k_sumexp() {
    __shared__ float sred[256];
    int n = blockIdx.x * blockDim.x + threadIdx.x;
    float gmax = dec_f(g_maxkey);
    float v = (n < N_NODES) ? expf(g_scores[n] - gmax) : 0.f;
    sred[threadIdx.x] = v;
    __syncthreads();
    for (int off = 128; off > 0; off >>= 1) {
        if (threadIdx.x < off) sred[threadIdx.x] += sred[threadIdx.x + off];
        __syncthreads();
    }
    if (threadIdx.x == 0) atomicAdd(&g_sumexp, sred[0]);
}

__global__ void k_attn() {
    int n = blockIdx.x * blockDim.x + threadIdx.x;
    if (n < N_NODES) {
        float gmax = dec_f(g_maxkey);
        g_attn[n] = expf(g_scores[n] - gmax) / g_sumexp;
    }
}

__global__ void k_gbounds() {
    int i = blockIdx.x * blockDim.x + threadIdx.x;
    if (i <= N_NODES) {
        int cur = (i < N_NODES) ? g_batch32[i] : NG;
        int prev = (i == 0) ? -1 : g_batch32[i - 1];
        for (int g = prev + 1; g <= cur && g <= NG; g++) g_gstart[g] = i;
    }
}

__global__ void k_pool() {
    int g = blockIdx.x, c = threadIdx.x;
    float acc = 0.f;
    int b = g_gstart[g], e = g_gstart[g + 1];
    for (int n = b; n < e; n++) acc += g_emb[(size_t)n * HID + c] * g_attn[n];
    g_gemb[g * HID + c] = acc;
}

// ------------------------- host launcher ------------------------------------
extern "C" void kernel_launch(void* const* d_in, const int* in_sizes, int n_in,
                              void* d_out, int out_size) {
    const float* x     = (const float*)d_in[0];
    const void*  ei    = d_in[1];
    const void*  et    = d_in[2];
    const void*  bt    = d_in[3];
    const float* W1    = (const float*)d_in[4];
    const float* root1 = (const float*)d_in[5];
    const float* b1    = (const float*)d_in[6];
    const float* W2    = (const float*)d_in[7];
    const float* root2 = (const float*)d_in[8];
    const float* b2    = (const float*)d_in[9];
    const float* W3    = (const float*)d_in[10];
    const float* root3 = (const float*)d_in[11];
    const float* b3    = (const float*)d_in[12];
    const float* g1    = (const float*)d_in[13];
    const float* beta1 = (const float*)d_in[14];
    const float* g2    = (const float*)d_in[15];
    const float* beta2 = (const float*)d_in[16];
    const float* A1    = (const float*)d_in[17];
    const float* a1    = (const float*)d_in[18];
    const float* A2    = (const float*)d_in[19];
    const float* a2    = (const float*)d_in[20];
    const float* C1    = (const float*)d_in[21];
    const float* c1    = (const float*)d_in[22];
    const float* C2    = (const float*)d_in[23];
    const float* c2    = (const float*)d_in[24];
    float* out = (float*)d_out;

    void *p_agg, *p_h, *p_raw, *p_emb, *p_gemb, *p_batch;
    cudaGetSymbolAddress(&p_agg, g_agg);
    cudaGetSymbolAddress(&p_h, g_h);
    cudaGetSymbolAddress(&p_raw, g_raw);
    cudaGetSymbolAddress(&p_emb, g_emb);
    cudaGetSymbolAddress(&p_gemb, g_gemb);
    cudaGetSymbolAddress(&p_batch, g_batch32);
    float* agg  = (float*)p_agg;
    float* h    = (float*)p_h;
    float* raw  = (float*)p_raw;
    float* emb  = (float*)p_emb;
    float* gemb = (float*)p_gemb;
    int* batch32 = (int*)p_batch;

    const int NB1 = (NRSEG + 1023) / 1024;   // 391

    // --- edge preprocessing (counting sort by segment) ---
    k_detect<<<1, 256>>>((const ull*)ei);
    k_zero_hist<<<(NRSEG + 255) / 256, 256>>>();
    k_edge_prep<<<(E_EDGES + 255) / 256, 256>>>(ei, et, bt);
    k_scan1<<<NB1, 256>>>();
    k_scan2<<<1, 512>>>(NB1);
    k_scan3<<<(NRSEG + 255) / 256, 256>>>();
    k_permute<<<(E_EDGES + 255) / 256, 256>>>();

    const int GEMM_BLOCKS = (N_NODES + BM - 1) / BM;   // 782
    const int AGG_BLOCKS = NRSEG / 8;                  // 50000

    // --- layer 1 ---
    k_aggregate<<<AGG_BLOCKS, 256>>>(x);
    k_zero_small<<<1, 256>>>();
    k_gemm<0, 1152><<<GEMM_BLOCKS, 256>>>(agg, x, nullptr, W1, root1, b1, raw);
    k_bnfin<<<1, 128>>>(g1, beta1);
    k_bnapply<<<(N_NODES * 32 + 255) / 256, 256>>>();

    // --- layer 2 ---
    k_aggregate<<<AGG_BLOCKS, 256>>>(h);
    k_zero_small<<<1, 256>>>();
    k_gemm<0, 1152><<<GEMM_BLOCKS, 256>>>(agg, h, nullptr, W2, root2, b2, raw);
    k_bnfin<<<1, 128>>>(g2, beta2);
    k_bnapply<<<(N_NODES * 32 + 255) / 256, 256>>>();

    // --- layer 3 (no BN) ---
    k_aggregate<<<AGG_BLOCKS, 256>>>(h);
    k_gemm<1, 1152><<<GEMM_BLOCKS, 256>>>(agg, h, nullptr, W3, root3, b3, emb);

    // --- attention pooling ---
    k_zero_small<<<1, 256>>>();
    k_scores<<<512, 256>>>(A1, a1, A2, a2);
    k_sumexp<<<(N_NODES + 255) / 256, 256>>>();
    k_attn<<<(N_NODES + 255) / 256, 256>>>();
    k_gbounds<<<(N_NODES + 256) / 256, 256>>>();
    k_pool<<<NG, 128>>>();

    // --- combiner MLP + row normalize ---
    k_gemm<2, 256><<<GEMM_BLOCKS, 256>>>(emb, gemb, batch32, C1, nullptr, c1, raw);
    k_gemm<3, 128><<<GEMM_BLOCKS, 256>>>(raw, nullptr, nullptr, C2, nullptr, c2, out);

    (void)in_sizes; (void)n_in; (void)out_size;
}

// round 4
// speedup vs baseline: 1.8073x; 1.8068x over previous
#include <cuda_runtime.h>
#include <cuda_bf16.h>
#include <stdint.h>

#define N_NODES 50000
#define E_EDGES 500000
#define R_REL 8
#define HID 128
#define NRSEG (N_NODES * R_REL)
#define NG 64
#define EPS_BN 1e-5f

typedef unsigned long long ull;

// ------------------------- device scratch ------------------------------------
__device__ __align__(16) __nv_bfloat16 g_agghi[(size_t)NRSEG * 128];
__device__ __align__(16) __nv_bfloat16 g_agglo[(size_t)NRSEG * 128];
__device__ __align__(16) float g_h[N_NODES * HID];
__device__ __align__(16) float g_raw[N_NODES * HID];
__device__ __align__(16) float g_emb[N_NODES * HID];
__device__ __align__(16) float g_gemb[NG * HID];
__device__ __align__(16) __nv_bfloat16 g_xhi[N_NODES * HID], g_xlo[N_NODES * HID];
__device__ __align__(16) __nv_bfloat16 g_hhi[N_NODES * HID], g_hlo[N_NODES * HID];
__device__ __align__(16) __nv_bfloat16 g_embhi[N_NODES * HID], g_emblo[N_NODES * HID];
__device__ __align__(16) __nv_bfloat16 g_t1hi[N_NODES * HID], g_t1lo[N_NODES * HID];
__device__ __align__(16) __nv_bfloat16 g_gembhi[NG * HID], g_gemblo[NG * HID];
__device__ __align__(16) __nv_bfloat16 g_w1hi[128 * 1152], g_w1lo[128 * 1152];
__device__ __align__(16) __nv_bfloat16 g_w2hi[128 * 1152], g_w2lo[128 * 1152];
__device__ __align__(16) __nv_bfloat16 g_w3hi[128 * 1152], g_w3lo[128 * 1152];
__device__ __align__(16) __nv_bfloat16 g_c1hi[128 * 256], g_c1lo[128 * 256];
__device__ __align__(16) __nv_bfloat16 g_c2hi[128 * 128], g_c2lo[128 * 128];

__device__ int   g_src32[E_EDGES];
__device__ int   g_segid[E_EDGES];
__device__ int   g_srcsorted[E_EDGES];
__device__ int   g_hist[NRSEG];
__device__ int   g_segstart[NRSEG + 1];
__device__ int   g_cursor[NRSEG];
__device__ float g_inv[NRSEG];
__device__ int   g_batch32[N_NODES];
__device__ int   g_gstart[NG + 1];
__device__ float g_scores[N_NODES];
__device__ float g_attn[N_NODES];
__device__ float g_colstats[2 * HID];
__device__ float g_bnscale[HID];
__device__ float g_bnshift[HID];
__device__ unsigned g_maxkey;
__device__ float g_sumexp;
__device__ int   g_is64;
__device__ int   g_bsums[512];

// ------------------------- helpers ------------------------------------------
__device__ __forceinline__ float lrelu(float x) { return x > 0.f ? x : 0.1f * x; }

__device__ __forceinline__ unsigned enc_f(float f) {
    unsigned b = __float_as_uint(f);
    return (b & 0x80000000u) ? ~b : (b | 0x80000000u);
}
__device__ __forceinline__ float dec_f(unsigned k) {
    unsigned b = (k & 0x80000000u) ? (k & 0x7FFFFFFFu) : ~k;
    return __uint_as_float(b);
}
__device__ __forceinline__ uint32_t smem_u32(const void* p) {
    return (uint32_t)__cvta_generic_to_shared(p);
}
__device__ __forceinline__ uint32_t pack_hi2(float a, float b, uint32_t& lopack) {
    __nv_bfloat16 h0 = __float2bfloat16(a);
    __nv_bfloat16 h1 = __float2bfloat16(b);
    __nv_bfloat16 l0 = __float2bfloat16(a - __bfloat162float(h0));
    __nv_bfloat16 l1 = __float2bfloat16(b - __bfloat162float(h1));
    lopack = (uint32_t)__bfloat16_as_ushort(l0) | ((uint32_t)__bfloat16_as_ushort(l1) << 16);
    return (uint32_t)__bfloat16_as_ushort(h0) | ((uint32_t)__bfloat16_as_ushort(h1) << 16);
}

// ------------------------- mma.sync / ldmatrix / cp.async --------------------
__device__ __forceinline__ void cp16(uint32_t dst, const void* src, uint32_t srcsz) {
    asm volatile("cp.async.ca.shared.global [%0], [%1], 16, %2;"
        :: "r"(dst), "l"(src), "r"(srcsz) : "memory");
}
__device__ __forceinline__ void cp_commit() {
    asm volatile("cp.async.commit_group;" ::: "memory");
}
__device__ __forceinline__ void cp_wait0() {
    asm volatile("cp.async.wait_group 0;" ::: "memory");
}
__device__ __forceinline__ void ldm4(uint32_t* r, uint32_t addr) {
    asm volatile("ldmatrix.sync.aligned.m8n8.x4.shared.b16 {%0,%1,%2,%3}, [%4];"
        : "=r"(r[0]), "=r"(r[1]), "=r"(r[2]), "=r"(r[3]) : "r"(addr));
}
__device__ __forceinline__ void mma16816(float* c, const uint32_t* a, const uint32_t* b) {
    asm volatile("mma.sync.aligned.m16n8k16.row.col.f32.bf16.bf16.f32 "
        "{%0,%1,%2,%3}, {%4,%5,%6,%7}, {%8,%9}, {%0,%1,%2,%3};"
        : "+f"(c[0]), "+f"(c[1]), "+f"(c[2]), "+f"(c[3])
        : "r"(a[0]), "r"(a[1]), "r"(a[2]), "r"(a[3]), "r"(b[0]), "r"(b[1]));
}

// ------------------------- dtype detection ----------------------------------
__global__ void k_detect(const ull* __restrict__ ei) {
    __shared__ unsigned s_is32;
    if (threadIdx.x == 0) s_is32 = 0;
    __syncthreads();
    ull m = 0;
    for (int i = threadIdx.x; i < 1024; i += 256) { ull v = ei[i]; m = v > m ? v : m; }
    if (m >= (1ull << 32)) atomicOr(&s_is32, 1u);
    __syncthreads();
    if (threadIdx.x == 0) g_is64 = s_is32 ? 0 : 1;
}

// ------------------------- edge preprocessing -------------------------------
__global__ void k_zero_hist() {
    int i = blockIdx.x * blockDim.x + threadIdx.x;
    if (i < NRSEG) g_hist[i] = 0;
}

__global__ void k_edge_prep(const void* __restrict__ ei, const void* __restrict__ et,
                            const void* __restrict__ bt) {
    int e = blockIdx.x * blockDim.x + threadIdx.x;
    int is64 = g_is64;
    if (e < E_EDGES) {
        int src, dst, ty;
        if (is64) {
            const long long* p = (const long long*)ei;
            src = (int)p[e]; dst = (int)p[E_EDGES + e];
            ty = (int)((const long long*)et)[e];
        } else {
            const int* p = (const int*)ei;
            src = p[e]; dst = p[E_EDGES + e];
            ty = ((const int*)et)[e];
        }
        g_src32[e] = src;
        int s = dst * R_REL + ty;
        g_segid[e] = s;
        atomicAdd(&g_hist[s], 1);
    }
    if (e < N_NODES)
        g_batch32[e] = is64 ? (int)((const long long*)bt)[e] : ((const int*)bt)[e];
}

__global__ void k_scan1() {
    __shared__ int sd[256];
    int t = threadIdx.x;
    int base = blockIdx.x * 1024 + t * 4;
    int v0 = 0, v1 = 0, v2 = 0, v3 = 0;
    if (base + 0 < NRSEG) v0 = g_hist[base + 0];
    if (base + 1 < NRSEG) v1 = g_hist[base + 1];
    if (base + 2 < NRSEG) v2 = g_hist[base + 2];
    if (base + 3 < NRSEG) v3 = g_hist[base + 3];
    int ts = v0 + v1 + v2 + v3;
    sd[t] = ts; __syncthreads();
    for (int off = 1; off < 256; off <<= 1) {
        int x = (t >= off) ? sd[t - off] : 0;
        __syncthreads();
        sd[t] += x;
        __syncthreads();
    }
    int ex = sd[t] - ts;
    if (base + 0 < NRSEG) g_segstart[base + 0] = ex;
    ex += v0; if (base + 1 < NRSEG) g_segstart[base + 1] = ex;
    ex += v1; if (base + 2 < NRSEG) g_segstart[base + 2] = ex;
    ex += v2; if (base + 3 < NRSEG) g_segstart[base + 3] = ex;
    if (t == 255) g_bsums[blockIdx.x] = sd[255];
}

__global__ void k_scan2(int nb) {
    __shared__ int sd[512];
    int t = threadIdx.x;
    int v = (t < nb) ? g_bsums[t] : 0;
    sd[t] = v; __syncthreads();
    for (int off = 1; off < 512; off <<= 1) {
        int x = (t >= off) ? sd[t - off] : 0;
        __syncthreads();
        sd[t] += x;
        __syncthreads();
    }
    if (t < nb) g_bsums[t] = sd[t] - v;
}

__global__ void k_scan3() {
    int i = blockIdx.x * blockDim.x + threadIdx.x;
    if (i < NRSEG) {
        int v = g_segstart[i] + g_bsums[i >> 10];
        g_segstart[i] = v;
        g_cursor[i] = v;
        int c = g_hist[i];
        g_inv[i] = 1.0f / (float)(c > 0 ? c : 1);
    }
    if (i == 0) g_segstart[NRSEG] = E_EDGES;
}

__global__ void k_permute() {
    int e = blockIdx.x * blockDim.x + threadIdx.x;
    if (e < E_EDGES) {
        int s = g_segid[e];
        int pos = atomicAdd(&g_cursor[s], 1);
        g_srcsorted[pos] = g_src32[e];
    }
}

// ------------------------- aggregation --------------------------------------
__global__ void __launch_bounds__(256) k_aggregate(const float* __restrict__ h) {
    int warp = (blockIdx.x * blockDim.x + threadIdx.x) >> 5;
    int lane = threadIdx.x & 31;
    if (warp >= NRSEG) return;
    int beg = g_segstart[warp], end = g_segstart[warp + 1];
    float4 acc = make_float4(0.f, 0.f, 0.f, 0.f);
    const float4* h4 = (const float4*)h;
    for (int e = beg; e < end; e++) {
        int s = g_srcsorted[e];
        float4 v = h4[s * 32 + lane];
        acc.x += v.x; acc.y += v.y; acc.z += v.z; acc.w += v.w;
    }
    float inv = g_inv[warp];
    acc.x *= inv; acc.y *= inv; acc.z *= inv; acc.w *= inv;
    uint2 hip, lop;
    hip.x = pack_hi2(acc.x, acc.y, lop.x);
    hip.y = pack_hi2(acc.z, acc.w, lop.y);
    size_t o = (size_t)warp * 32 + lane;
    ((uint2*)g_agghi)[o] = hip;
    ((uint2*)g_agglo)[o] = lop;
}

// ------------------------- fp32 -> bf16 hi/lo split ---------------------------
__global__ void k_split(const float* __restrict__ src, __nv_bfloat16* __restrict__ hi,
                        __nv_bfloat16* __restrict__ lo, int total4) {
    int i = blockIdx.x * blockDim.x + threadIdx.x;
    if (i < total4) {
        float4 v = ((const float4*)src)[i];
        uint2 hp, lp;
        hp.x = pack_hi2(v.x, v.y, lp.x);
        hp.y = pack_hi2(v.z, v.w, lp.y);
        ((uint2*)hi)[i] = hp;
        ((uint2*)lo)[i] = lp;
    }
}

// ------------------------- weight prep ---------------------------------------
__global__ void k_wprep(const float* __restrict__ W, const float* __restrict__ root,
                        __nv_bfloat16* __restrict__ bh, __nv_bfloat16* __restrict__ bl) {
    int idx = blockIdx.x * blockDim.x + threadIdx.x;
    if (idx < 128 * 1152) {
        int c = idx / 1152, k = idx % 1152;
        float v = (k < 1024) ? W[((k >> 7) * 128 + (k & 127)) * 128 + c]
                             : root[(k - 1024) * 128 + c];
        __nv_bfloat16 h = __float2bfloat16(v);
        bh[idx] = h;
        bl[idx] = __float2bfloat16(v - __bfloat162float(h));
    }
}

template <int K>
__global__ void k_cprep(const float* __restrict__ C, __nv_bfloat16* __restrict__ bh,
                        __nv_bfloat16* __restrict__ bl) {
    int idx = blockIdx.x * blockDim.x + threadIdx.x;
    if (idx < 128 * K) {
        int c = idx / K, k = idx % K;
        float v = C[k * 128 + c];
        __nv_bfloat16 h = __float2bfloat16(v);
        bh[idx] = h;
        bl[idx] = __float2bfloat16(v - __bfloat162float(h));
    }
}

// ------------------------- mma.sync GEMM -------------------------------------
// 128x128 CTA tile, 256 thr, warp grid 4(M)x2(N), warp tile 32x64.
// D = Ahi*Bhi^T + Ahi*Blo^T + Alo*Bhi^T (fp32 acc).
// MODE 0: +BN stats, out=raw. MODE 1: out=emb fp32 + hi/lo.
// MODE 2: A=[emb|gemb[batch]], lrelu, out hi/lo. MODE 3: row-norm -> outf.
#define BKC 32
#define ROWB 80          // smem bytes per tile row (32 bf16 + 16B pad)
#define TILE_B 10240     // 128 * 80
#define BUF_B 40960      // 4 tiles
#define CP 132           // staging row stride (floats)

template <int MODE, int KT>
__global__ void __launch_bounds__(256, 2) k_mgemm(
    const __nv_bfloat16* __restrict__ Ahi, const __nv_bfloat16* __restrict__ Alo,
    const __nv_bfloat16* __restrict__ A2hi, const __nv_bfloat16* __restrict__ A2lo,
    const int* __restrict__ batch,
    const __nv_bfloat16* __restrict__ Bhi, const __nv_bfloat16* __restrict__ Blo,
    const float* __restrict__ bias,
    float* __restrict__ outf,
    __nv_bfloat16* __restrict__ ohi, __nv_bfloat16* __restrict__ olo) {
    constexpr int NCH = KT / BKC;
    extern __shared__ __align__(16) char dsm[];
    __shared__ float s_bias[128];
    __shared__ float s_stat[256];

    int tid = threadIdx.x;
    int bm = blockIdx.x * 128;
    int wid = tid >> 5, lane = tid & 31;
    int mo = (wid & 3) * 32;
    int no = (wid >> 2) * 64;
    uint32_t sbase = smem_u32(dsm);

    if (tid < 128) s_bias[tid] = bias[tid];
    if (MODE == 0) s_stat[tid] = 0.f;
    if (MODE == 0 && tid + 128 < 256) s_stat[tid + 128] = 0.f;

    float acc[2][8][4];
#pragma unroll
    for (int mi = 0; mi < 2; mi++)
#pragma unroll
        for (int j = 0; j < 8; j++)
#pragma unroll
            for (int q = 0; q < 4; q++) acc[mi][j][q] = 0.f;

    // ---- chunk loader (cp.async) ----
    auto loadChunk = [&](int i) {
        int b = i & 1;
        uint32_t sb = sbase + b * BUF_B;
        int k0 = i * BKC;
#pragma unroll
        for (int it = 0; it < 2; it++) {
            int idx = it * 256 + tid;
            int row = idx >> 2, seg = idx & 3;
            // A
            int n = bm + row;
            bool v = (n < N_NODES);
            int nn = v ? n : 0;
            const __nv_bfloat16 *ph, *pl;
            if (MODE <= 1) {
                if (k0 < 1024) { ph = Ahi + (size_t)nn * 1024 + k0; pl = Alo + (size_t)nn * 1024 + k0; }
                else { ph = A2hi + (size_t)nn * 128 + (k0 - 1024); pl = A2lo + (size_t)nn * 128 + (k0 - 1024); }
            } else if (MODE == 2) {
                if (k0 < 128) { ph = Ahi + (size_t)nn * 128 + k0; pl = Alo + (size_t)nn * 128 + k0; }
                else {
                    int g = v ? batch[nn] : 0;
                    ph = A2hi + (size_t)g * 128 + (k0 - 128);
                    pl = A2lo + (size_t)g * 128 + (k0 - 128);
                }
            } else {
                ph = Ahi + (size_t)nn * 128 + k0;
                pl = Alo + (size_t)nn * 128 + k0;
            }
            uint32_t sz = v ? 16u : 0u;
            uint32_t da = sb + (uint32_t)(row * ROWB + seg * 16);
            cp16(da, ph + seg * 8, sz);
            cp16(da + TILE_B, pl + seg * 8, sz);
            // B (weights, 128 rows, stride KT)
            uint32_t db = sb + 2 * TILE_B + (uint32_t)(row * ROWB + seg * 16);
            cp16(db, Bhi + (size_t)row * KT + k0 + seg * 8, 16u);
            cp16(db + TILE_B, Blo + (size_t)row * KT + k0 + seg * 8, 16u);
        }
        cp_commit();
    };

    loadChunk(0);
    for (int i = 0; i < NCH; i++) {
        cp_wait0();
        __syncthreads();
        if (i + 1 < NCH) loadChunk(i + 1);
        uint32_t ab = sbase + (uint32_t)((i & 1) * BUF_B);
#pragma unroll
        for (int kk = 0; kk < 2; kk++) {
            uint32_t ah[2][4], al[2][4];
#pragma unroll
            for (int mi = 0; mi < 2; mi++) {
                uint32_t r = (uint32_t)(mo + mi * 16 + (lane & 15));
                uint32_t c = (uint32_t)(kk * 16 + (lane >> 4) * 8);
                uint32_t ad = ab + r * ROWB + c * 2;
                ldm4(ah[mi], ad);
                ldm4(al[mi], ad + TILE_B);
            }
#pragma unroll
            for (int jp = 0; jp < 4; jp++) {
                uint32_t r = (uint32_t)(no + jp * 16 + (lane & 15));
                uint32_t c = (uint32_t)(kk * 16 + (lane >> 4) * 8);
                uint32_t bd = ab + 2 * TILE_B + r * ROWB + c * 2;
                uint32_t t[4], u[4];
                ldm4(t, bd);
                ldm4(u, bd + TILE_B);
                uint32_t bh0[2] = {t[0], t[2]}, bh1[2] = {t[1], t[3]};
                uint32_t bl0[2] = {u[0], u[2]}, bl1[2] = {u[1], u[3]};
#pragma unroll
                for (int mi = 0; mi < 2; mi++) {
                    mma16816(acc[mi][jp * 2 + 0], ah[mi], bh0);
                    mma16816(acc[mi][jp * 2 + 0], ah[mi], bl0);
                    mma16816(acc[mi][jp * 2 + 0], al[mi], bh0);
                    mma16816(acc[mi][jp * 2 + 1], ah[mi], bh1);
                    mma16816(acc[mi][jp * 2 + 1], ah[mi], bl1);
                    mma16816(acc[mi][jp * 2 + 1], al[mi], bh1);
                }
            }
        }
        __syncthreads();
    }

    // ---- stage accumulators to smem (reuse tile buffers) ----
    float* Cs = (float*)dsm;
#pragma unroll
    for (int mi = 0; mi < 2; mi++)
#pragma unroll
        for (int j = 0; j < 8; j++) {
            int r0 = mo + mi * 16 + (lane >> 2);
            int col = no + j * 8 + (lane & 3) * 2;
            *(float2*)&Cs[r0 * CP + col] = make_float2(acc[mi][j][0], acc[mi][j][1]);
            *(float2*)&Cs[(r0 + 8) * CP + col] = make_float2(acc[mi][j][2], acc[mi][j][3]);
        }
    __syncthreads();

    // ---- per-row epilogue: threads 0..127 own row tid ----
    if (tid < 128) {
        int n = bm + tid;
        bool valid = (n < N_NODES);
        const float* crow = &Cs[tid * CP];

        if (MODE == 3) {
            float ss = 0.f;
#pragma unroll 8
            for (int c = 0; c < 128; c++) {
                float v = crow[c] + s_bias[c];
                ss += v * v;
            }
            float sc = 1.f / fmaxf(sqrtf(ss), 1e-12f);
            if (valid) {
#pragma unroll
                for (int c4 = 0; c4 < 32; c4++) {
                    float4 o;
                    o.x = (crow[c4 * 4 + 0] + s_bias[c4 * 4 + 0]) * sc;
                    o.y = (crow[c4 * 4 + 1] + s_bias[c4 * 4 + 1]) * sc;
                    o.z = (crow[c4 * 4 + 2] + s_bias[c4 * 4 + 2]) * sc;
                    o.w = (crow[c4 * 4 + 3] + s_bias[c4 * 4 + 3]) * sc;
                    *(float4*)&outf[(size_t)n * 128 + c4 * 4] = o;
                }
            }
        } else {
#pragma unroll
            for (int cb = 0; cb < 4; cb++) {
                float vf[32];
#pragma unroll
                for (int j = 0; j < 32; j++) {
                    float v = crow[cb * 32 + j] + s_bias[cb * 32 + j];
                    if (MODE == 2) v = lrelu(v);
                    vf[j] = v;
                }
                if (MODE == 0) {
#pragma unroll
                    for (int j = 0; j < 32; j++) {
                        float a_ = valid ? vf[j] : 0.f;
                        float q_ = valid ? vf[j] * vf[j] : 0.f;
#pragma unroll
                        for (int off = 16; off > 0; off >>= 1) {
                            a_ += __shfl_xor_sync(0xffffffffu, a_, off);
                            q_ += __shfl_xor_sync(0xffffffffu, q_, off);
                        }
                        if ((tid & 31) == 0) {
                            atomicAdd(&s_stat[cb * 32 + j], a_);
                            atomicAdd(&s_stat[128 + cb * 32 + j], q_);
                        }
                    }
                }
                if (valid) {
                    if (MODE == 0 || MODE == 1) {
#pragma unroll
                        for (int j4 = 0; j4 < 8; j4++)
                            *(float4*)&outf[(size_t)n * 128 + cb * 32 + j4 * 4] =
                                make_float4(vf[j4 * 4], vf[j4 * 4 + 1], vf[j4 * 4 + 2], vf[j4 * 4 + 3]);
                    }
                    if (MODE == 1 || MODE == 2) {
                        uint32_t* phh = (uint32_t*)(ohi + (size_t)n * 128 + cb * 32);
                        uint32_t* pll = (uint32_t*)(olo + (size_t)n * 128 + cb * 32);
#pragma unroll
                        for (int j2 = 0; j2 < 16; j2++) {
                            uint32_t lp;
                            uint32_t hp = pack_hi2(vf[j2 * 2], vf[j2 * 2 + 1], lp);
                            phh[j2] = hp;
                            pll[j2] = lp;
                        }
                    }
                }
            }
        }
    }
    __syncthreads();
    if (MODE == 0 && tid < 256) atomicAdd(&g_colstats[tid], s_stat[tid]);
}

// ------------------------- BN ------------------------------------------------
__global__ void k_zero_small() {
    int t = threadIdx.x;
    if (t < 256) g_colstats[t] = 0.f;
    if (t == 0) { g_maxkey = 0u; g_sumexp = 0.f; }
}

__global__ void k_bnfin(const float* __restrict__ gamma, const float* __restrict__ beta) {
    int c = threadIdx.x;
    if (c < HID) {
        float inv_n = 1.f / (float)N_NODES;
        float mu = g_colstats[c] * inv_n;
        float var = fmaxf(g_colstats[HID + c] * inv_n - mu * mu, 0.f);
        float sc = gamma[c] * rsqrtf(var + EPS_BN);
        g_bnscale[c] = sc;
        g_bnshift[c] = beta[c] - mu * sc;
    }
}

__global__ void k_bnapply() {
    int i = blockIdx.x * blockDim.x + threadIdx.x;
    if (i < N_NODES * 32) {
        float4 v = ((const float4*)g_raw)[i];
        int c4 = i & 31;
        float4 sc = ((const float4*)g_bnscale)[c4];
        float4 sh = ((const float4*)g_bnshift)[c4];
        float4 o;
        o.x = lrelu(v.x * sc.x + sh.x);
        o.y = lrelu(v.y * sc.y + sh.y);
        o.z = lrelu(v.z * sc.z + sh.z);
        o.w = lrelu(v.w * sc.w + sh.w);
        ((float4*)g_h)[i] = o;
        uint2 hp, lp;
        hp.x = pack_hi2(o.x, o.y, lp.x);
        hp.y = pack_hi2(o.z, o.w, lp.y);
        ((uint2*)g_hhi)[i] = hp;
        ((uint2*)g_hlo)[i] = lp;
    }
}

// ------------------------- attention ------------------------------------------
__global__ void __launch_bounds__(256) k_scores(const float* __restrict__ A1,
                                                const float* __restrict__ a1,
                                                const float* __restrict__ A2,
                                                const float* __restrict__ a2v) {
    __shared__ float sA1[HID * 64];
    __shared__ float sA2[64];
    __shared__ float sa1[64];
    __shared__ float se[8][HID];
    __shared__ unsigned s_bmax;
    int tid = threadIdx.x;
    for (int i = tid; i < HID * 64; i += 256) sA1[i] = A1[i];
    if (tid < 64) { sA2[tid] = A2[tid]; sa1[tid] = a1[tid]; }
    if (tid == 0) s_bmax = 0u;
    __syncthreads();
    int w = tid >> 5, lane = tid & 31;
    unsigned localmax = 0u;
    float a2s = a2v[0];
    for (int n = blockIdx.x * 8 + w; n < N_NODES; n += gridDim.x * 8) {
        for (int i = lane; i < HID; i += 32) se[w][i] = g_emb[(size_t)n * HID + i];
        __syncwarp();
        float acc0 = 0.f, acc1 = 0.f;
#pragma unroll 8
        for (int k = 0; k < HID; k++) {
            float e = se[w][k];
            acc0 = fmaf(e, sA1[k * 64 + lane], acc0);
            acc1 = fmaf(e, sA1[k * 64 + lane + 32], acc1);
        }
        acc0 = lrelu(acc0 + sa1[lane]);
        acc1 = lrelu(acc1 + sa1[lane + 32]);
        float part = acc0 * sA2[lane] + acc1 * sA2[lane + 32];
#pragma unroll
        for (int off = 16; off > 0; off >>= 1) part += __shfl_down_sync(0xFFFFFFFFu, part, off);
        if (lane == 0) {
            float s = part + a2s;
            g_scores[n] = s;
            unsigned k = enc_f(s);
            localmax = k > localmax ? k : localmax;
        }
        __syncwarp();
    }
    if (lane == 0 && localmax) atomicMax(&s_bmax, localmax);
    __syncthreads();
    if (tid == 0) atomicMax(&g_maxkey, s_bmax);
}

__global__ void k_sumexp() {
    __shared__ float sred[256];
    int n = blockIdx.x * blockDim.x + threadIdx.x;
    float gmax = dec_f(g_maxkey);
    float v = (n < N_NODES) ? expf(g_scores[n] - gmax) : 0.f;
    sred[threadIdx.x] = v;
    __syncthreads();
    for (int off = 128; off > 0; off >>= 1) {
        if (threadIdx.x < off) sred[threadIdx.x] += sred[threadIdx.x + off];
        __syncthreads();
    }
    if (threadIdx.x == 0) atomicAdd(&g_sumexp, sred[0]);
}

__global__ void k_attn() {
    int n = blockIdx.x * blockDim.x + threadIdx.x;
    if (n < N_NODES) {
        float gmax = dec_f(g_maxkey);
        g_attn[n] = expf(g_scores[n] - gmax) / g_sumexp;
    }
}

__global__ void k_gbounds() {
    int i = blockIdx.x * blockDim.x + threadIdx.x;
    if (i <= N_NODES) {
        int cur = (i < N_NODES) ? g_batch32[i] : NG;
        int prev = (i == 0) ? -1 : g_batch32[i - 1];
        for (int g = prev + 1; g <= cur && g <= NG; g++) g_gstart[g] = i;
    }
}

__global__ void k_pool() {
    int g = blockIdx.x, c = threadIdx.x;
    float acc = 0.f;
    int b = g_gstart[g], e = g_gstart[g + 1];
    for (int n = b; n < e; n++) acc += g_emb[(size_t)n * HID + c] * g_attn[n];
    g_gemb[g * HID + c] = acc;
}

// ------------------------- host launcher --------------------------------------
extern "C" void kernel_launch(void* const* d_in, const int* in_sizes, int n_in,
                              void* d_out, int out_size) {
    const float* x     = (const float*)d_in[0];
    const void*  ei    = d_in[1];
    const void*  et    = d_in[2];
    const void*  bt    = d_in[3];
    const float* W1    = (const float*)d_in[4];
    const float* root1 = (const float*)d_in[5];
    const float* b1    = (const float*)d_in[6];
    const float* W2    = (const float*)d_in[7];
    const float* root2 = (const float*)d_in[8];
    const float* b2    = (const float*)d_in[9];
    const float* W3    = (const float*)d_in[10];
    const float* root3 = (const float*)d_in[11];
    const float* b3    = (const float*)d_in[12];
    const float* g1    = (const float*)d_in[13];
    const float* beta1 = (const float*)d_in[14];
    const float* g2    = (const float*)d_in[15];
    const float* beta2 = (const float*)d_in[16];
    const float* A1    = (const float*)d_in[17];
    const float* a1    = (const float*)d_in[18];
    const float* A2    = (const float*)d_in[19];
    const float* a2    = (const float*)d_in[20];
    const float* C1    = (const float*)d_in[21];
    const float* c1    = (const float*)d_in[22];
    const float* C2    = (const float*)d_in[23];
    const float* c2    = (const float*)d_in[24];
    float* out = (float*)d_out;

    void* p;
    cudaGetSymbolAddress(&p, g_agghi);  __nv_bfloat16* agghi = (__nv_bfloat16*)p;
    cudaGetSymbolAddress(&p, g_agglo);  __nv_bfloat16* agglo = (__nv_bfloat16*)p;
    cudaGetSymbolAddress(&p, g_h);      float* h    = (float*)p;
    cudaGetSymbolAddress(&p, g_raw);    float* raw  = (float*)p;
    cudaGetSymbolAddress(&p, g_emb);    float* emb  = (float*)p;
    cudaGetSymbolAddress(&p, g_gemb);   float* gemb = (float*)p;
    cudaGetSymbolAddress(&p, g_xhi);    __nv_bfloat16* xhi = (__nv_bfloat16*)p;
    cudaGetSymbolAddress(&p, g_xlo);    __nv_bfloat16* xlo = (__nv_bfloat16*)p;
    cudaGetSymbolAddress(&p, g_hhi);    __nv_bfloat16* hhi = (__nv_bfloat16*)p;
    cudaGetSymbolAddress(&p, g_hlo);    __nv_bfloat16* hlo = (__nv_bfloat16*)p;
    cudaGetSymbolAddress(&p, g_embhi);  __nv_bfloat16* embhi = (__nv_bfloat16*)p;
    cudaGetSymbolAddress(&p, g_emblo);  __nv_bfloat16* emblo = (__nv_bfloat16*)p;
    cudaGetSymbolAddress(&p, g_t1hi);   __nv_bfloat16* t1hi = (__nv_bfloat16*)p;
    cudaGetSymbolAddress(&p, g_t1lo);   __nv_bfloat16* t1lo = (__nv_bfloat16*)p;
    cudaGetSymbolAddress(&p, g_gembhi); __nv_bfloat16* gembhi = (__nv_bfloat16*)p;
    cudaGetSymbolAddress(&p, g_gemblo); __nv_bfloat16* gemblo = (__nv_bfloat16*)p;
    cudaGetSymbolAddress(&p, g_w1hi);   __nv_bfloat16* w1hi = (__nv_bfloat16*)p;
    cudaGetSymbolAddress(&p, g_w1lo);   __nv_bfloat16* w1lo = (__nv_bfloat16*)p;
    cudaGetSymbolAddress(&p, g_w2hi);   __nv_bfloat16* w2hi = (__nv_bfloat16*)p;
    cudaGetSymbolAddress(&p, g_w2lo);   __nv_bfloat16* w2lo = (__nv_bfloat16*)p;
    cudaGetSymbolAddress(&p, g_w3hi);   __nv_bfloat16* w3hi = (__nv_bfloat16*)p;
    cudaGetSymbolAddress(&p, g_w3lo);   __nv_bfloat16* w3lo = (__nv_bfloat16*)p;
    cudaGetSymbolAddress(&p, g_c1hi);   __nv_bfloat16* c1hi = (__nv_bfloat16*)p;
    cudaGetSymbolAddress(&p, g_c1lo);   __nv_bfloat16* c1lo = (__nv_bfloat16*)p;
    cudaGetSymbolAddress(&p, g_c2hi);   __nv_bfloat16* c2hi = (__nv_bfloat16*)p;
    cudaGetSymbolAddress(&p, g_c2lo);   __nv_bfloat16* c2lo = (__nv_bfloat16*)p;
    cudaGetSymbolAddress(&p, g_batch32); int* batch32 = (int*)p;

    const int DSM = 2 * BUF_B;   // 81920 bytes (>= staging 128*132*4)
    cudaFuncSetAttribute(k_mgemm<0, 1152>, cudaFuncAttributeMaxDynamicSharedMemorySize, DSM);
    cudaFuncSetAttribute(k_mgemm<1, 1152>, cudaFuncAttributeMaxDynamicSharedMemorySize, DSM);
    cudaFuncSetAttribute(k_mgemm<2, 256>,  cudaFuncAttributeMaxDynamicSharedMemorySize, DSM);
    cudaFuncSetAttribute(k_mgemm<3, 128>,  cudaFuncAttributeMaxDynamicSharedMemorySize, DSM);

    const int NB1 = (NRSEG + 1023) / 1024;

    k_detect<<<1, 256>>>((const ull*)ei);
    k_zero_hist<<<(NRSEG + 255) / 256, 256>>>();
    k_edge_prep<<<(E_EDGES + 255) / 256, 256>>>(ei, et, bt);
    k_scan1<<<NB1, 256>>>();
    k_scan2<<<1, 512>>>(NB1);
    k_scan3<<<(NRSEG + 255) / 256, 256>>>();
    k_permute<<<(E_EDGES + 255) / 256, 256>>>();

    k_wprep<<<(128 * 1152 + 255) / 256, 256>>>(W1, root1, w1hi, w1lo);
    k_wprep<<<(128 * 1152 + 255) / 256, 256>>>(W2, root2, w2hi, w2lo);
    k_wprep<<<(128 * 1152 + 255) / 256, 256>>>(W3, root3, w3hi, w3lo);
    k_cprep<256><<<(128 * 256 + 255) / 256, 256>>>(C1, c1hi, c1lo);
    k_cprep<128><<<(128 * 128 + 255) / 256, 256>>>(C2, c2hi, c2lo);
    k_split<<<(N_NODES * 32 + 255) / 256, 256>>>(x, xhi, xlo, N_NODES * 32);

    const int GB = (N_NODES + 127) / 128;   // 391
    const int AGG_BLOCKS = NRSEG / 8;       // 50000

    // layer 1
    k_aggregate<<<AGG_BLOCKS, 256>>>(x);
    k_zero_small<<<1, 256>>>();
    k_mgemm<0, 1152><<<GB, 256, DSM>>>(agghi, agglo, xhi, xlo, nullptr,
                                       w1hi, w1lo, b1, raw, nullptr, nullptr);
    k_bnfin<<<1, 128>>>(g1, beta1);
    k_bnapply<<<(N_NODES * 32 + 255) / 256, 256>>>();

    // layer 2
    k_aggregate<<<AGG_BLOCKS, 256>>>(h);
    k_zero_small<<<1, 256>>>();
    k_mgemm<0, 1152><<<GB, 256, DSM>>>(agghi, agglo, hhi, hlo, nullptr,
                                       w2hi, w2lo, b2, raw, nullptr, nullptr);
    k_bnfin<<<1, 128>>>(g2, beta2);
    k_bnapply<<<(N_NODES * 32 + 255) / 256, 256>>>();

    // layer 3
    k_aggregate<<<AGG_BLOCKS, 256>>>(h);
    k_mgemm<1, 1152><<<GB, 256, DSM>>>(agghi, agglo, hhi, hlo, nullptr,
                                       w3hi, w3lo, b3, emb, embhi, emblo);

    // attention pooling
    k_zero_small<<<1, 256>>>();
    k_scores<<<512, 256>>>(A1, a1, A2, a2);
    k_sumexp<<<(N_NODES + 255) / 256, 256>>>();
    k_attn<<<(N_NODES + 255) / 256, 256>>>();
    k_gbounds<<<(N_NODES + 256) / 256, 256>>>();
    k_pool<<<NG, 128>>>();
    k_split<<<(NG * 32 + 255) / 256, 256>>>(gemb, gembhi, gemblo, NG * 32);

    // combiner MLP + row normalize
    k_mgemm<2, 256><<<GB, 256, DSM>>>(embhi, emblo, gembhi, gemblo, batch32,
                                      c1hi, c1lo, c1, nullptr, t1hi, t1lo);
    k_mgemm<3, 128><<<GB, 256, DSM>>>(t1hi, t1lo, nullptr, nullptr, nullptr,
                                      c2hi, c2lo, c2, out, nullptr, nullptr);

    (void)in_sizes; (void)n_in; (void)out_size;
}

// round 5
// speedup vs baseline: 2.3844x; 1.3193x over previous
#include <cuda_runtime.h>
#include <cuda_fp16.h>
#include <stdint.h>

#define N_NODES 50000
#define E_EDGES 500000
#define R_REL 8
#define HID 128
#define NRSEG (N_NODES * R_REL)
#define NG 64
#define EPS_BN 1e-5f

typedef unsigned long long ull;

// ------------------------- device scratch ------------------------------------
__device__ __align__(16) __half g_aggh[(size_t)NRSEG * 128];    // 102.4MB
__device__ __align__(16) float g_raw[N_NODES * HID];
__device__ __align__(16) float g_emb[N_NODES * HID];
__device__ __align__(16) float g_gemb[NG * HID];
__device__ __align__(16) __half g_xh[N_NODES * HID];
__device__ __align__(16) __half g_hh[N_NODES * HID];
__device__ __align__(16) __half g_embh[N_NODES * HID];
__device__ __align__(16) __half g_t1h[N_NODES * HID];
__device__ __align__(16) __half g_gembh[NG * HID];
__device__ __align__(16) __half g_w1hi[128 * 1152], g_w1lo[128 * 1152];
__device__ __align__(16) __half g_w2hi[128 * 1152], g_w2lo[128 * 1152];
__device__ __align__(16) __half g_w3hi[128 * 1152], g_w3lo[128 * 1152];
__device__ __align__(16) __half g_c1hi[128 * 256], g_c1lo[128 * 256];
__device__ __align__(16) __half g_c2hi[128 * 128], g_c2lo[128 * 128];

__device__ int   g_src32[E_EDGES];
__device__ int   g_segid[E_EDGES];
__device__ int   g_srcsorted[E_EDGES];
__device__ int   g_hist[NRSEG];          // static zero-init; scan3 re-zeroes
__device__ int   g_segstart[NRSEG + 1];
__device__ int   g_cursor[NRSEG];
__device__ float g_inv[NRSEG];
__device__ int   g_batch32[N_NODES];
__device__ int   g_gstart[NG + 1];
__device__ float g_scores[N_NODES];
__device__ float g_attn[N_NODES];
__device__ float g_colstats[2 * HID];
__device__ float g_bnscale[HID];
__device__ float g_bnshift[HID];
__device__ unsigned g_maxkey;
__device__ float g_sumexp;
__device__ int   g_is64;
__device__ int   g_bsums[512];

// ------------------------- helpers ------------------------------------------
__device__ __forceinline__ float lrelu(float x) { return x > 0.f ? x : 0.1f * x; }

__device__ __forceinline__ unsigned enc_f(float f) {
    unsigned b = __float_as_uint(f);
    return (b & 0x80000000u) ? ~b : (b | 0x80000000u);
}
__device__ __forceinline__ float dec_f(unsigned k) {
    unsigned b = (k & 0x80000000u) ? (k & 0x7FFFFFFFu) : ~k;
    return __uint_as_float(b);
}
__device__ __forceinline__ uint32_t smem_u32(const void* p) {
    return (uint32_t)__cvta_generic_to_shared(p);
}
__device__ __forceinline__ uint32_t pk_h2(float a, float b) {
    __half2 h = __float22half2_rn(make_float2(a, b));
    return *(uint32_t*)&h;
}

// ------------------------- mma.sync / ldmatrix / cp.async --------------------
__device__ __forceinline__ void cp16(uint32_t dst, const void* src, uint32_t srcsz) {
    asm volatile("cp.async.ca.shared.global [%0], [%1], 16, %2;"
        :: "r"(dst), "l"(src), "r"(srcsz) : "memory");
}
__device__ __forceinline__ void cp_commit() {
    asm volatile("cp.async.commit_group;" ::: "memory");
}
__device__ __forceinline__ void cp_wait0() {
    asm volatile("cp.async.wait_group 0;" ::: "memory");
}
__device__ __forceinline__ void ldm4(uint32_t* r, uint32_t addr) {
    asm volatile("ldmatrix.sync.aligned.m8n8.x4.shared.b16 {%0,%1,%2,%3}, [%4];"
        : "=r"(r[0]), "=r"(r[1]), "=r"(r[2]), "=r"(r[3]) : "r"(addr));
}
__device__ __forceinline__ void mma16816(float* c, const uint32_t* a, const uint32_t* b) {
    asm volatile("mma.sync.aligned.m16n8k16.row.col.f32.f16.f16.f32 "
        "{%0,%1,%2,%3}, {%4,%5,%6,%7}, {%8,%9}, {%0,%1,%2,%3};"
        : "+f"(c[0]), "+f"(c[1]), "+f"(c[2]), "+f"(c[3])
        : "r"(a[0]), "r"(a[1]), "r"(a[2]), "r"(a[3]), "r"(b[0]), "r"(b[1]));
}

// ------------------------- dtype detection ----------------------------------
__global__ void k_detect(const ull* __restrict__ ei) {
    __shared__ unsigned s_is32;
    if (threadIdx.x == 0) s_is32 = 0;
    __syncthreads();
    ull m = 0;
    for (int i = threadIdx.x; i < 1024; i += 256) { ull v = ei[i]; m = v > m ? v : m; }
    if (m >= (1ull << 32)) atomicOr(&s_is32, 1u);
    __syncthreads();
    if (threadIdx.x == 0) g_is64 = s_is32 ? 0 : 1;
}

// ------------------------- edge preprocessing -------------------------------
__global__ void k_edge_prep(const void* __restrict__ ei, const void* __restrict__ et,
                            const void* __restrict__ bt) {
    int e = blockIdx.x * blockDim.x + threadIdx.x;
    int is64 = g_is64;
    if (e < E_EDGES) {
        int src, dst, ty;
        if (is64) {
            const long long* p = (const long long*)ei;
            src = (int)p[e]; dst = (int)p[E_EDGES + e];
            ty = (int)((const long long*)et)[e];
        } else {
            const int* p = (const int*)ei;
            src = p[e]; dst = p[E_EDGES + e];
            ty = ((const int*)et)[e];
        }
        g_src32[e] = src;
        int s = dst * R_REL + ty;
        g_segid[e] = s;
        atomicAdd(&g_hist[s], 1);
    }
    if (e < N_NODES)
        g_batch32[e] = is64 ? (int)((const long long*)bt)[e] : ((const int*)bt)[e];
}

__global__ void k_scan1() {
    __shared__ int sd[256];
    int t = threadIdx.x;
    int base = blockIdx.x * 1024 + t * 4;
    int v0 = 0, v1 = 0, v2 = 0, v3 = 0;
    if (base + 0 < NRSEG) v0 = g_hist[base + 0];
    if (base + 1 < NRSEG) v1 = g_hist[base + 1];
    if (base + 2 < NRSEG) v2 = g_hist[base + 2];
    if (base + 3 < NRSEG) v3 = g_hist[base + 3];
    int ts = v0 + v1 + v2 + v3;
    sd[t] = ts; __syncthreads();
    for (int off = 1; off < 256; off <<= 1) {
        int x = (t >= off) ? sd[t - off] : 0;
        __syncthreads();
        sd[t] += x;
        __syncthreads();
    }
    int ex = sd[t] - ts;
    if (base + 0 < NRSEG) g_segstart[base + 0] = ex;
    ex += v0; if (base + 1 < NRSEG) g_segstart[base + 1] = ex;
    ex += v1; if (base + 2 < NRSEG) g_segstart[base + 2] = ex;
    ex += v2; if (base + 3 < NRSEG) g_segstart[base + 3] = ex;
    if (t == 255) g_bsums[blockIdx.x] = sd[255];
}

__global__ void k_scan2(int nb) {
    __shared__ int sd[512];
    int t = threadIdx.x;
    int v = (t < nb) ? g_bsums[t] : 0;
    sd[t] = v; __syncthreads();
    for (int off = 1; off < 512; off <<= 1) {
        int x = (t >= off) ? sd[t - off] : 0;
        __syncthreads();
        sd[t] += x;
        __syncthreads();
    }
    if (t < nb) g_bsums[t] = sd[t] - v;
}

__global__ void k_scan3() {
    int i = blockIdx.x * blockDim.x + threadIdx.x;
    if (i < NRSEG) {
        int v = g_segstart[i] + g_bsums[i >> 10];
        g_segstart[i] = v;
        g_cursor[i] = v;
        int c = g_hist[i];
        g_inv[i] = 1.0f / (float)(c > 0 ? c : 1);
        g_hist[i] = 0;            // self-clear for next graph replay
    }
    if (i == 0) g_segstart[NRSEG] = E_EDGES;
}

__global__ void k_permute() {
    int e = blockIdx.x * blockDim.x + threadIdx.x;
    if (e < E_EDGES) {
        int s = g_segid[e];
        int pos = atomicAdd(&g_cursor[s], 1);
        g_srcsorted[pos] = g_src32[e];
    }
}

// ------------------------- aggregation (gathers fp16, sums fp32) ------------
__global__ void __launch_bounds__(256) k_aggregate(const __half* __restrict__ hsrc) {
    int warp = (blockIdx.x * blockDim.x + threadIdx.x) >> 5;
    int lane = threadIdx.x & 31;
    if (warp >= NRSEG) return;
    int beg = g_segstart[warp], end = g_segstart[warp + 1];
    float ax = 0.f, ay = 0.f, az = 0.f, aw = 0.f;
    for (int e = beg; e < end; e++) {
        int s = g_srcsorted[e];
        uint2 v = ((const uint2*)(hsrc + (size_t)s * 128))[lane];
        float2 f0 = __half22float2(*(__half2*)&v.x);
        float2 f1 = __half22float2(*(__half2*)&v.y);
        ax += f0.x; ay += f0.y; az += f1.x; aw += f1.y;
    }
    float inv = g_inv[warp];
    uint2 o;
    o.x = pk_h2(ax * inv, ay * inv);
    o.y = pk_h2(az * inv, aw * inv);
    ((uint2*)g_aggh)[(size_t)warp * 32 + lane] = o;
}

// ------------------------- fp32 -> fp16 --------------------------------------
__global__ void k_tohalf(const float* __restrict__ src, __half* __restrict__ dst, int total4) {
    int i = blockIdx.x * blockDim.x + threadIdx.x;
    if (i < total4) {
        float4 v = ((const float4*)src)[i];
        uint2 o;
        o.x = pk_h2(v.x, v.y);
        o.y = pk_h2(v.z, v.w);
        ((uint2*)dst)[i] = o;
    }
}

// ------------------------- weight prep (fp16 hi/lo split) --------------------
__global__ void k_wprep(const float* __restrict__ W, const float* __restrict__ root,
                        __half* __restrict__ bh, __half* __restrict__ bl) {
    int idx = blockIdx.x * blockDim.x + threadIdx.x;
    if (idx < 128 * 1152) {
        int c = idx / 1152, k = idx % 1152;
        float v = (k < 1024) ? W[((k >> 7) * 128 + (k & 127)) * 128 + c]
                             : root[(k - 1024) * 128 + c];
        __half h = __float2half_rn(v);
        bh[idx] = h;
        bl[idx] = __float2half_rn(v - __half2float(h));
    }
}

template <int K>
__global__ void k_cprep(const float* __restrict__ C, __half* __restrict__ bh,
                        __half* __restrict__ bl) {
    int idx = blockIdx.x * blockDim.x + threadIdx.x;
    if (idx < 128 * K) {
        int c = idx / K, k = idx % K;
        float v = C[k * 128 + c];
        __half h = __float2half_rn(v);
        bh[idx] = h;
        bl[idx] = __float2half_rn(v - __half2float(h));
    }
}

// ------------------------- mma.sync GEMM (fp16, 2 products) ------------------
// 128x128 CTA tile, 256 thr, warp grid 4(M)x2(N), warp tile 32x64.
// D = A*Bhi^T + A*Blo^T (fp32 acc); A single fp16, B split fp16.
// MODE 0: +BN stats, out=raw. MODE 1: out=emb fp32 + embh.
// MODE 2: A=[embh|gembh[batch]], lrelu, out=t1h. MODE 3: row-norm -> outf.
#define BKC 32
#define ROWB 80          // smem bytes per tile row (32 fp16 + 16B pad)
#define TILE_B 10240     // 128 * 80
#define BUF_B 30720      // 3 tiles (A, Bhi, Blo)
#define CP 132           // staging row stride (floats)

template <int MODE, int KT>
__global__ void __launch_bounds__(256, 2) k_mgemm(
    const __half* __restrict__ A, const __half* __restrict__ A2,
    const int* __restrict__ batch,
    const __half* __restrict__ Bhi, const __half* __restrict__ Blo,
    const float* __restrict__ bias,
    float* __restrict__ outf, __half* __restrict__ oh) {
    constexpr int NCH = KT / BKC;
    extern __shared__ __align__(16) char dsm[];
    __shared__ float s_bias[128];
    __shared__ float s_stat[256];

    int tid = threadIdx.x;
    int bm = blockIdx.x * 128;
    int wid = tid >> 5, lane = tid & 31;
    int mo = (wid & 3) * 32;
    int no = (wid >> 2) * 64;
    uint32_t sbase = smem_u32(dsm);

    if (tid < 128) s_bias[tid] = bias[tid];
    if (MODE == 0) { s_stat[tid] = 0.f; if (tid < 0) {} }
    if (MODE == 0 && tid + 128 < 256) s_stat[tid + 128] = 0.f;

    float acc[2][8][4];
#pragma unroll
    for (int mi = 0; mi < 2; mi++)
#pragma unroll
        for (int j = 0; j < 8; j++)
#pragma unroll
            for (int q = 0; q < 4; q++) acc[mi][j][q] = 0.f;

    auto loadChunk = [&](int i) {
        int b = i & 1;
        uint32_t sb = sbase + b * BUF_B;
        int k0 = i * BKC;
#pragma unroll
        for (int it = 0; it < 2; it++) {
            int idx = it * 256 + tid;
            int row = idx >> 2, seg = idx & 3;
            // A
            int n = bm + row;
            bool v = (n < N_NODES);
            int nn = v ? n : 0;
            const __half* pa;
            if (MODE <= 1) {
                pa = (k0 < 1024) ? A + (size_t)nn * 1024 + k0
                                 : A2 + (size_t)nn * 128 + (k0 - 1024);
            } else if (MODE == 2) {
                if (k0 < 128) pa = A + (size_t)nn * 128 + k0;
                else {
                    int g = v ? batch[nn] : 0;
                    pa = A2 + (size_t)g * 128 + (k0 - 128);
                }
            } else {
                pa = A + (size_t)nn * 128 + k0;
            }
            cp16(sb + (uint32_t)(row * ROWB + seg * 16), pa + seg * 8, v ? 16u : 0u);
            // B hi / lo
            uint32_t db = sb + TILE_B + (uint32_t)(row * ROWB + seg * 16);
            cp16(db, Bhi + (size_t)row * KT + k0 + seg * 8, 16u);
            cp16(db + TILE_B, Blo + (size_t)row * KT + k0 + seg * 8, 16u);
        }
        cp_commit();
    };

    loadChunk(0);
    for (int i = 0; i < NCH; i++) {
        cp_wait0();
        __syncthreads();
        if (i + 1 < NCH) loadChunk(i + 1);
        uint32_t ab = sbase + (uint32_t)((i & 1) * BUF_B);
#pragma unroll
        for (int kk = 0; kk < 2; kk++) {
            uint32_t a[2][4];
#pragma unroll
            for (int mi = 0; mi < 2; mi++) {
                uint32_t r = (uint32_t)(mo + mi * 16 + (lane & 15));
                uint32_t c = (uint32_t)(kk * 16 + (lane >> 4) * 8);
                ldm4(a[mi], ab + r * ROWB + c * 2);
            }
#pragma unroll
            for (int jp = 0; jp < 4; jp++) {
                uint32_t r = (uint32_t)(no + jp * 16 + (lane & 15));
                uint32_t c = (uint32_t)(kk * 16 + (lane >> 4) * 8);
                uint32_t bd = ab + TILE_B + r * ROWB + c * 2;
                uint32_t t[4], u[4];
                ldm4(t, bd);
                ldm4(u, bd + TILE_B);
                uint32_t bh0[2] = {t[0], t[2]}, bh1[2] = {t[1], t[3]};
                uint32_t bl0[2] = {u[0], u[2]}, bl1[2] = {u[1], u[3]};
#pragma unroll
                for (int mi = 0; mi < 2; mi++) {
                    mma16816(acc[mi][jp * 2 + 0], a[mi], bh0);
                    mma16816(acc[mi][jp * 2 + 0], a[mi], bl0);
                    mma16816(acc[mi][jp * 2 + 1], a[mi], bh1);
                    mma16816(acc[mi][jp * 2 + 1], a[mi], bl1);
                }
            }
        }
        __syncthreads();
    }

    // ---- stage accumulators to smem ----
    float* Cs = (float*)dsm;
#pragma unroll
    for (int mi = 0; mi < 2; mi++)
#pragma unroll
        for (int j = 0; j < 8; j++) {
            int r0 = mo + mi * 16 + (lane >> 2);
            int col = no + j * 8 + (lane & 3) * 2;
            *(float2*)&Cs[r0 * CP + col] = make_float2(acc[mi][j][0], acc[mi][j][1]);
            *(float2*)&Cs[(r0 + 8) * CP + col] = make_float2(acc[mi][j][2], acc[mi][j][3]);
        }
    __syncthreads();

    // ---- per-row epilogue: threads 0..127 own row tid ----
    if (tid < 128) {
        int n = bm + tid;
        bool valid = (n < N_NODES);
        const float* crow = &Cs[tid * CP];

        if (MODE == 3) {
            float ss = 0.f;
#pragma unroll 8
            for (int c = 0; c < 128; c++) {
                float v = crow[c] + s_bias[c];
                ss += v * v;
            }
            float sc = 1.f / fmaxf(sqrtf(ss), 1e-12f);
            if (valid) {
#pragma unroll
                for (int c4 = 0; c4 < 32; c4++) {
                    float4 o;
                    o.x = (crow[c4 * 4 + 0] + s_bias[c4 * 4 + 0]) * sc;
                    o.y = (crow[c4 * 4 + 1] + s_bias[c4 * 4 + 1]) * sc;
                    o.z = (crow[c4 * 4 + 2] + s_bias[c4 * 4 + 2]) * sc;
                    o.w = (crow[c4 * 4 + 3] + s_bias[c4 * 4 + 3]) * sc;
                    *(float4*)&outf[(size_t)n * 128 + c4 * 4] = o;
                }
            }
        } else {
#pragma unroll
            for (int cb = 0; cb < 4; cb++) {
                float vf[32];
#pragma unroll
                for (int j = 0; j < 32; j++) {
                    float v = crow[cb * 32 + j] + s_bias[cb * 32 + j];
                    if (MODE == 2) v = lrelu(v);
                    vf[j] = v;
                }
                if (MODE == 0) {
#pragma unroll
                    for (int j = 0; j < 32; j++) {
                        float a_ = valid ? vf[j] : 0.f;
                        float q_ = valid ? vf[j] * vf[j] : 0.f;
#pragma unroll
                        for (int off = 16; off > 0; off >>= 1) {
                            a_ += __shfl_xor_sync(0xffffffffu, a_, off);
                            q_ += __shfl_xor_sync(0xffffffffu, q_, off);
                        }
                        if ((tid & 31) == 0) {
                            atomicAdd(&s_stat[cb * 32 + j], a_);
                            atomicAdd(&s_stat[128 + cb * 32 + j], q_);
                        }
                    }
                }
                if (valid) {
                    if (MODE == 0 || MODE == 1) {
#pragma unroll
                        for (int j4 = 0; j4 < 8; j4++)
                            *(float4*)&outf[(size_t)n * 128 + cb * 32 + j4 * 4] =
                                make_float4(vf[j4 * 4], vf[j4 * 4 + 1], vf[j4 * 4 + 2], vf[j4 * 4 + 3]);
                    }
                    if (MODE == 1 || MODE == 2) {
                        uint32_t* ph = (uint32_t*)(oh + (size_t)n * 128 + cb * 32);
#pragma unroll
                        for (int j2 = 0; j2 < 16; j2++)
                            ph[j2] = pk_h2(vf[j2 * 2], vf[j2 * 2 + 1]);
                    }
                }
            }
        }
    }
    __syncthreads();
    if (MODE == 0 && tid < 256) atomicAdd(&g_colstats[tid], s_stat[tid]);
}

// ------------------------- BN ------------------------------------------------
__global__ void k_zero_small() {
    int t = threadIdx.x;
    if (t < 256) g_colstats[t] = 0.f;
    if (t == 0) { g_maxkey = 0u; g_sumexp = 0.f; }
}

__global__ void k_bnfin(const float* __restrict__ gamma, const float* __restrict__ beta) {
    int c = threadIdx.x;
    if (c < HID) {
        float inv_n = 1.f / (float)N_NODES;
        float mu = g_colstats[c] * inv_n;
        float var = fmaxf(g_colstats[HID + c] * inv_n - mu * mu, 0.f);
        float sc = gamma[c] * rsqrtf(var + EPS_BN);
        g_bnscale[c] = sc;
        g_bnshift[c] = beta[c] - mu * sc;
    }
}

__global__ void k_bnapply() {
    int i = blockIdx.x * blockDim.x + threadIdx.x;
    if (i < N_NODES * 32) {
        float4 v = ((const float4*)g_raw)[i];
        int c4 = i & 31;
        float4 sc = ((const float4*)g_bnscale)[c4];
        float4 sh = ((const float4*)g_bnshift)[c4];
        float ox = lrelu(v.x * sc.x + sh.x);
        float oy = lrelu(v.y * sc.y + sh.y);
        float oz = lrelu(v.z * sc.z + sh.z);
        float ow = lrelu(v.w * sc.w + sh.w);
        uint2 o;
        o.x = pk_h2(ox, oy);
        o.y = pk_h2(oz, ow);
        ((uint2*)g_hh)[i] = o;
    }
}

// ------------------------- attention ------------------------------------------
__global__ void __launch_bounds__(256) k_scores(const float* __restrict__ A1,
                                                const float* __restrict__ a1,
                                                const float* __restrict__ A2,
                                                const float* __restrict__ a2v) {
    __shared__ float sA1[HID * 64];
    __shared__ float sA2[64];
    __shared__ float sa1[64];
    __shared__ float se[8][HID];
    __shared__ unsigned s_bmax;
    int tid = threadIdx.x;
    for (int i = tid; i < HID * 64; i += 256) sA1[i] = A1[i];
    if (tid < 64) { sA2[tid] = A2[tid]; sa1[tid] = a1[tid]; }
    if (tid == 0) s_bmax = 0u;
    __syncthreads();
    int w = tid >> 5, lane = tid & 31;
    unsigned localmax = 0u;
    float a2s = a2v[0];
    for (int n = blockIdx.x * 8 + w; n < N_NODES; n += gridDim.x * 8) {
        for (int i = lane; i < HID; i += 32) se[w][i] = g_emb[(size_t)n * HID + i];
        __syncwarp();
        float acc0 = 0.f, acc1 = 0.f;
#pragma unroll 8
        for (int k = 0; k < HID; k++) {
            float e = se[w][k];
            acc0 = fmaf(e, sA1[k * 64 + lane], acc0);
            acc1 = fmaf(e, sA1[k * 64 + lane + 32], acc1);
        }
        acc0 = lrelu(acc0 + sa1[lane]);
        acc1 = lrelu(acc1 + sa1[lane + 32]);
        float part = acc0 * sA2[lane] + acc1 * sA2[lane + 32];
#pragma unroll
        for (int off = 16; off > 0; off >>= 1) part += __shfl_down_sync(0xFFFFFFFFu, part, off);
        if (lane == 0) {
            float s = part + a2s;
            g_scores[n] = s;
            unsigned k = enc_f(s);
            localmax = k > localmax ? k : localmax;
        }
        __syncwarp();
    }
    if (lane == 0 && localmax) atomicMax(&s_bmax, localmax);
    __syncthreads();
    if (tid == 0) atomicMax(&g_maxkey, s_bmax);
}

__global__ void k_sumexp() {
    __shared__ float sred[256];
    int n = blockIdx.x * blockDim.x + threadIdx.x;
    float gmax = dec_f(g_maxkey);
    float v = (n < N_NODES) ? expf(g_scores[n] - gmax) : 0.f;
    sred[threadIdx.x] = v;
    __syncthreads();
    for (int off = 128; off > 0; off >>= 1) {
        if (threadIdx.x < off) sred[threadIdx.x] += sred[threadIdx.x + off];
        __syncthreads();
    }
    if (threadIdx.x == 0) atomicAdd(&g_sumexp, sred[0]);
}

__global__ void k_attn() {
    int n = blockIdx.x * blockDim.x + threadIdx.x;
    if (n < N_NODES) {
        float gmax = dec_f(g_maxkey);
        g_attn[n] = expf(g_scores[n] - gmax) / g_sumexp;
    }
}

__global__ void k_gbounds() {
    int i = blockIdx.x * blockDim.x + threadIdx.x;
    if (i <= N_NODES) {
        int cur = (i < N_NODES) ? g_batch32[i] : NG;
        int prev = (i == 0) ? -1 : g_batch32[i - 1];
        for (int g = prev + 1; g <= cur && g <= NG; g++) g_gstart[g] = i;
    }
}

__global__ void k_pool() {
    int g = blockIdx.x, c = threadIdx.x;
    float acc = 0.f;
    int b = g_gstart[g], e = g_gstart[g + 1];
    for (int n = b; n < e; n++) acc += g_emb[(size_t)n * HID + c] * g_attn[n];
    g_gemb[g * HID + c] = acc;
}

// ------------------------- host launcher --------------------------------------
extern "C" void kernel_launch(void* const* d_in, const int* in_sizes, int n_in,
                              void* d_out, int out_size) {
    const float* x     = (const float*)d_in[0];
    const void*  ei    = d_in[1];
    const void*  et    = d_in[2];
    const void*  bt    = d_in[3];
    const float* W1    = (const float*)d_in[4];
    const float* root1 = (const float*)d_in[5];
    const float* b1    = (const float*)d_in[6];
    const float* W2    = (const float*)d_in[7];
    const float* root2 = (const float*)d_in[8];
    const float* b2    = (const float*)d_in[9];
    const float* W3    = (const float*)d_in[10];
    const float* root3 = (const float*)d_in[11];
    const float* b3    = (const float*)d_in[12];
    const float* g1    = (const float*)d_in[13];
    const float* beta1 = (const float*)d_in[14];
    const float* g2    = (const float*)d_in[15];
    const float* beta2 = (const float*)d_in[16];
    const float* A1    = (const float*)d_in[17];
    const float* a1    = (const float*)d_in[18];
    const float* A2    = (const float*)d_in[19];
    const float* a2    = (const float*)d_in[20];
    const float* C1    = (const float*)d_in[21];
    const float* c1    = (const float*)d_in[22];
    const float* C2    = (const float*)d_in[23];
    const float* c2    = (const float*)d_in[24];
    float* out = (float*)d_out;

    void* p;
    cudaGetSymbolAddress(&p, g_aggh);   __half* aggh = (__half*)p;
    cudaGetSymbolAddress(&p, g_raw);    float* raw  = (float*)p;
    cudaGetSymbolAddress(&p, g_emb);    float* emb  = (float*)p;
    cudaGetSymbolAddress(&p, g_gemb);   float* gemb = (float*)p;
    cudaGetSymbolAddress(&p, g_xh);     __half* xh = (__half*)p;
    cudaGetSymbolAddress(&p, g_hh);     __half* hh = (__half*)p;
    cudaGetSymbolAddress(&p, g_embh);   __half* embh = (__half*)p;
    cudaGetSymbolAddress(&p, g_t1h);    __half* t1h = (__half*)p;
    cudaGetSymbolAddress(&p, g_gembh);  __half* gembh = (__half*)p;
    cudaGetSymbolAddress(&p, g_w1hi);   __half* w1hi = (__half*)p;
    cudaGetSymbolAddress(&p, g_w1lo);   __half* w1lo = (__half*)p;
    cudaGetSymbolAddress(&p, g_w2hi);   __half* w2hi = (__half*)p;
    cudaGetSymbolAddress(&p, g_w2lo);   __half* w2lo = (__half*)p;
    cudaGetSymbolAddress(&p, g_w3hi);   __half* w3hi = (__half*)p;
    cudaGetSymbolAddress(&p, g_w3lo);   __half* w3lo = (__half*)p;
    cudaGetSymbolAddress(&p, g_c1hi);   __half* c1hi = (__half*)p;
    cudaGetSymbolAddress(&p, g_c1lo);   __half* c1lo = (__half*)p;
    cudaGetSymbolAddress(&p, g_c2hi);   __half* c2hi = (__half*)p;
    cudaGetSymbolAddress(&p, g_c2lo);   __half* c2lo = (__half*)p;
    cudaGetSymbolAddress(&p, g_batch32); int* batch32 = (int*)p;

    const int DSM = 128 * CP * 4;   // 67584 B: covers 2*BUF_B (61440) and staging
    cudaFuncSetAttribute(k_mgemm<0, 1152>, cudaFuncAttributeMaxDynamicSharedMemorySize, DSM);
    cudaFuncSetAttribute(k_mgemm<1, 1152>, cudaFuncAttributeMaxDynamicSharedMemorySize, DSM);
    cudaFuncSetAttribute(k_mgemm<2, 256>,  cudaFuncAttributeMaxDynamicSharedMemorySize, DSM);
    cudaFuncSetAttribute(k_mgemm<3, 128>,  cudaFuncAttributeMaxDynamicSharedMemorySize, DSM);

    const int NB1 = (NRSEG + 1023) / 1024;

    k_detect<<<1, 256>>>((const ull*)ei);
    k_edge_prep<<<(E_EDGES + 255) / 256, 256>>>(ei, et, bt);
    k_scan1<<<NB1, 256>>>();
    k_scan2<<<1, 512>>>(NB1);
    k_scan3<<<(NRSEG + 255) / 256, 256>>>();
    k_permute<<<(E_EDGES + 255) / 256, 256>>>();

    k_wprep<<<(128 * 1152 + 255) / 256, 256>>>(W1, root1, w1hi, w1lo);
    k_wprep<<<(128 * 1152 + 255) / 256, 256>>>(W2, root2, w2hi, w2lo);
    k_wprep<<<(128 * 1152 + 255) / 256, 256>>>(W3, root3, w3hi, w3lo);
    k_cprep<256><<<(128 * 256 + 255) / 256, 256>>>(C1, c1hi, c1lo);
    k_cprep<128><<<(128 * 128 + 255) / 256, 256>>>(C2, c2hi, c2lo);
    k_tohalf<<<(N_NODES * 32 + 255) / 256, 256>>>(x, xh, N_NODES * 32);

    const int GB = (N_NODES + 127) / 128;   // 391
    const int AGG_BLOCKS = NRSEG / 8;       // 50000

    // layer 1
    k_aggregate<<<AGG_BLOCKS, 256>>>(xh);
    k_zero_small<<<1, 256>>>();
    k_mgemm<0, 1152><<<GB, 256, DSM>>>(aggh, xh, nullptr, w1hi, w1lo, b1, raw, nullptr);
    k_bnfin<<<1, 128>>>(g1, beta1);
    k_bnapply<<<(N_NODES * 32 + 255) / 256, 256>>>();

    // layer 2
    k_aggregate<<<AGG_BLOCKS, 256>>>(hh);
    k_zero_small<<<1, 256>>>();
    k_mgemm<0, 1152><<<GB, 256, DSM>>>(aggh, hh, nullptr, w2hi, w2lo, b2, raw, nullptr);
    k_bnfin<<<1, 128>>>(g2, beta2);
    k_bnapply<<<(N_NODES * 32 + 255) / 256, 256>>>();

    // layer 3
    k_aggregate<<<AGG_BLOCKS, 256>>>(hh);
    k_mgemm<1, 1152><<<GB, 256, DSM>>>(aggh, hh, nullptr, w3hi, w3lo, b3, emb, embh);

    // attention pooling
    k_zero_small<<<1, 256>>>();
    k_scores<<<512, 256>>>(A1, a1, A2, a2);
    k_sumexp<<<(N_NODES + 255) / 256, 256>>>();
    k_attn<<<(N_NODES + 255) / 256, 256>>>();
    k_gbounds<<<(N_NODES + 256) / 256, 256>>>();
    k_pool<<<NG, 128>>>();
    k_tohalf<<<(NG * 32 + 255) / 256, 256>>>(gemb, gembh, NG * 32);

    // combiner MLP + row normalize
    k_mgemm<2, 256><<<GB, 256, DSM>>>(embh, gembh, batch32, c1hi, c1lo, c1, nullptr, t1h);
    k_mgemm<3, 128><<<GB, 256, DSM>>>(t1h, nullptr, nullptr, c2hi, c2lo, c2, out, nullptr);

    (void)in_sizes; (void)n_in; (void)out_size;
}